// round 14
// baseline (speedup 1.0000x reference)
#include <cuda_runtime.h>
#include <cstdint>

// ---------------------------------------------------------------------------
// Problem constants
// ---------------------------------------------------------------------------
#define T_  4
#define B_  4
#define C_  512
#define N_  1024          // H*W
#define NH_ 8
#define HD_ 64
#define TBAT (T_*B_)
#define BCN  (B_*C_*N_)
#define CC   (C_*C_)
#define EPS_ 1e-5f
#define FULLW 0xffffffffu

// ---------------------------------------------------------------------------
// Device scratch (static — no allocation anywhere)
// Spikes live as bitmasks: row layout [tb][n][16 c-words] (bit = c&31).
// ---------------------------------------------------------------------------
__device__ float    g_wt[4 * CC];          // W^T per branch: [w][c][d]
__device__ uint32_t g_bx[TBAT * N_ * 16];  // input spike bits
__device__ uint32_t g_bq[TBAT * N_ * 16];  // q spike bits
__device__ uint32_t g_bk[TBAT * N_ * 16];  // k spike bits
__device__ uint32_t g_bv[TBAT * N_ * 16];  // v spike bits
__device__ uint32_t g_mk[TBAT * C_ * 32];  // k bits reoriented: [tb][c][32 n-words]
__device__ uint32_t g_mv[TBAT * C_ * 32];
__device__ float    g_kv[TBAT * NH_ * HD_ * HD_];  // [tb*8+h][e][dd], carries x0.125

// ---------------------------------------------------------------------------
// Weight transpose (all 4 branches): W[d][c] -> g_wt[w][c][d]
// ---------------------------------------------------------------------------
__global__ __launch_bounds__(256)
void prep_wt_kernel(const float* __restrict__ Wq, const float* __restrict__ Wk,
                    const float* __restrict__ Wv, const float* __restrict__ Wp)
{
    int w = blockIdx.z;
    const float* src = (w == 0) ? Wq : (w == 1) ? Wk : (w == 2) ? Wv : Wp;
    float* dst = g_wt + (size_t)w * CC;
    int d0 = blockIdx.y * 32, c0 = blockIdx.x * 32;
    int tx = threadIdx.x & 31, ty = threadIdx.x >> 5;
    __shared__ float s[32][33];
    #pragma unroll
    for (int r = 0; r < 4; r++)
        s[ty + 8 * r][tx] = src[(size_t)(d0 + ty + 8 * r) * C_ + c0 + tx];
    __syncthreads();
    #pragma unroll
    for (int r = 0; r < 4; r++)
        dst[(size_t)(c0 + ty + 8 * r) * C_ + d0 + tx] = s[tx][ty + 8 * r];
}

// ---------------------------------------------------------------------------
// Input LIF -> spike BITS.  x fp32 [t,b,c,n] -> g_bx[tb][n][c-word], vth=1.
// ---------------------------------------------------------------------------
__global__ __launch_bounds__(256)
void lif_in_bits_kernel(const float* __restrict__ x)
{
    int b  = blockIdx.z;
    int c0 = blockIdx.y * 32;
    int n0 = blockIdx.x * 32;
    int tx = threadIdx.x & 31, ty = threadIdx.x >> 5;
    int warp = threadIdx.x >> 5, lane = threadIdx.x & 31;
    __shared__ float s[32][33];
    float v[4] = {0.f, 0.f, 0.f, 0.f};

    for (int t = 0; t < T_; t++) {
        #pragma unroll
        for (int r = 0; r < 4; r++) {
            int c = c0 + ty + 8 * r;
            float xv = x[(((size_t)t * B_ + b) * C_ + c) * (size_t)N_ + n0 + tx];
            float vv = v[r];
            vv = fmaf(xv - vv, 0.5f, vv);
            float sp = (vv >= 1.0f) ? 1.f : 0.f;
            v[r] = (vv >= 1.0f) ? 0.f : vv;
            s[ty + 8 * r][tx] = sp;
        }
        __syncthreads();
        int tb = t * B_ + b;
        #pragma unroll
        for (int r = 0; r < 4; r++) {
            int nl = warp * 4 + r;
            uint32_t word = __ballot_sync(FULLW, s[lane][nl] != 0.f);
            if (lane == 0)
                g_bx[((size_t)tb * N_ + n0 + nl) * 16 + (c0 >> 5)] = word;
        }
        __syncthreads();
    }
}

// ---------------------------------------------------------------------------
// Pack 4 spike bits/thread into 16 words across 128 threads, store to gmem.
// ---------------------------------------------------------------------------
__device__ __forceinline__ void store_bits(uint32_t* __restrict__ grow,
                                           uint32_t nib, int tid, int lane)
{
    uint32_t contrib = nib << (4 * (lane & 7));
    contrib |= __shfl_xor_sync(FULLW, contrib, 1);
    contrib |= __shfl_xor_sync(FULLW, contrib, 2);
    contrib |= __shfl_xor_sync(FULLW, contrib, 4);
    if ((lane & 7) == 0) grow[tid >> 3] = contrib;
}

// ---------------------------------------------------------------------------
// Union list build over NT n-rows: entries c | (flags<<16), ascending c.
// nmask[j][16] must be filled and synced by caller.
// ---------------------------------------------------------------------------
template <int NT>
__device__ __forceinline__ int decode_union(const uint32_t (*nmask)[16],
                                            uint32_t* unionw, uint32_t* list32,
                                            int* basew, int* cntp)
{
    int tid = threadIdx.x, warp = tid >> 5, lane = tid & 31;
    if (tid < 16) {
        uint32_t u = 0;
        #pragma unroll
        for (int j = 0; j < NT; j++) u |= nmask[j][tid];
        unionw[tid] = u;
    }
    __syncthreads();
    if (tid == 0) {
        int s = 0;
        #pragma unroll
        for (int ci = 0; ci < 16; ci++) { basew[ci] = s; s += __popc(unionw[ci]); }
        *cntp = s;
    }
    __syncthreads();
    #pragma unroll
    for (int ci = warp; ci < 16; ci += 4) {
        uint32_t m = unionw[ci];
        if (m & (1u << lane)) {
            uint32_t flags = 0;
            #pragma unroll
            for (int j = 0; j < NT; j++)
                flags |= ((nmask[j][ci] >> lane) & 1u) << j;
            list32[basew[ci] + __popc(m & ((1u << lane) - 1u))] =
                (uint32_t)(ci * 32 + lane) | (flags << 16);
        }
    }
    __syncthreads();
    return *cntp;
}

// ---------------------------------------------------------------------------
// Fused Q/K/V union-gather (4-n tile) + BN + LIF (vth=1) -> spike BITS.
// Block = (b, n0=4*blockIdx.x), 128 threads; thread owns c = 4*tid..4*tid+3.
// ---------------------------------------------------------------------------
#define NTQ 4

__global__ __launch_bounds__(128)
void gather_qkv_lif_kernel(const float* __restrict__ qg, const float* __restrict__ qb,
                           const float* __restrict__ qm, const float* __restrict__ qv,
                           const float* __restrict__ kg, const float* __restrict__ kb,
                           const float* __restrict__ km, const float* __restrict__ kv,
                           const float* __restrict__ vg, const float* __restrict__ vb,
                           const float* __restrict__ vm, const float* __restrict__ vv)
{
    int b = blockIdx.y, n0 = blockIdx.x * NTQ;
    int tid = threadIdx.x, lane = tid & 31;

    __shared__ __align__(16) uint32_t nmask[NTQ][16];
    __shared__ __align__(16) uint32_t unionw[16];
    __shared__ __align__(16) uint32_t list32[C_];
    __shared__ int basew[16];
    __shared__ int cnt;

    const float4* Wq4 = (const float4*)(g_wt + 0 * (size_t)CC);
    const float4* Wk4 = (const float4*)(g_wt + 1 * (size_t)CC);
    const float4* Wv4 = (const float4*)(g_wt + 2 * (size_t)CC);

    float4 qs_c, qs_h, ks_c, ks_h, vs_c, vs_h;
    {
        float4 g = ((const float4*)qg)[tid], bb = ((const float4*)qb)[tid];
        float4 m = ((const float4*)qm)[tid], v = ((const float4*)qv)[tid];
        qs_c.x = g.x * rsqrtf(v.x + EPS_); qs_h.x = bb.x - m.x * qs_c.x;
        qs_c.y = g.y * rsqrtf(v.y + EPS_); qs_h.y = bb.y - m.y * qs_c.y;
        qs_c.z = g.z * rsqrtf(v.z + EPS_); qs_h.z = bb.z - m.z * qs_c.z;
        qs_c.w = g.w * rsqrtf(v.w + EPS_); qs_h.w = bb.w - m.w * qs_c.w;
    }
    {
        float4 g = ((const float4*)kg)[tid], bb = ((const float4*)kb)[tid];
        float4 m = ((const float4*)km)[tid], v = ((const float4*)kv)[tid];
        ks_c.x = g.x * rsqrtf(v.x + EPS_); ks_h.x = bb.x - m.x * ks_c.x;
        ks_c.y = g.y * rsqrtf(v.y + EPS_); ks_h.y = bb.y - m.y * ks_c.y;
        ks_c.z = g.z * rsqrtf(v.z + EPS_); ks_h.z = bb.z - m.z * ks_c.z;
        ks_c.w = g.w * rsqrtf(v.w + EPS_); ks_h.w = bb.w - m.w * ks_c.w;
    }
    {
        float4 g = ((const float4*)vg)[tid], bb = ((const float4*)vb)[tid];
        float4 m = ((const float4*)vm)[tid], v = ((const float4*)vv)[tid];
        vs_c.x = g.x * rsqrtf(v.x + EPS_); vs_h.x = bb.x - m.x * vs_c.x;
        vs_c.y = g.y * rsqrtf(v.y + EPS_); vs_h.y = bb.y - m.y * vs_c.y;
        vs_c.z = g.z * rsqrtf(v.z + EPS_); vs_h.z = bb.z - m.z * vs_c.z;
        vs_c.w = g.w * rsqrtf(v.w + EPS_); vs_h.w = bb.w - m.w * vs_c.w;
    }

    float4 mq[NTQ], mk[NTQ], mv[NTQ];
    #pragma unroll
    for (int j = 0; j < NTQ; j++) {
        mq[j] = make_float4(0.f, 0.f, 0.f, 0.f);
        mk[j] = mq[j]; mv[j] = mq[j];
    }

    for (int t = 0; t < T_; t++) {
        int tb = t * B_ + b;
        size_t rbase0 = ((size_t)tb * N_ + n0) * 16;

        // load per-n input masks
        if (tid < NTQ * 16) {
            int j = tid >> 4, ci = tid & 15;
            nmask[j][ci] = g_bx[rbase0 + (size_t)j * 16 + ci];
        }
        __syncthreads();
        int count = decode_union<NTQ>(nmask, unionw, list32, basew, &cnt);

        float4 aq[NTQ], ak[NTQ], av[NTQ];
        #pragma unroll
        for (int j = 0; j < NTQ; j++) {
            aq[j] = make_float4(0.f, 0.f, 0.f, 0.f);
            ak[j] = aq[j]; av[j] = aq[j];
        }

        for (int i = 0; i < count; i++) {
            uint32_t e = list32[i];
            int c = e & 0xffff;
            uint32_t f = e >> 16;
            float4 wq = Wq4[(size_t)c * 128 + tid];
            float4 wk = Wk4[(size_t)c * 128 + tid];
            float4 wv = Wv4[(size_t)c * 128 + tid];
            #pragma unroll
            for (int j = 0; j < NTQ; j++) {
                if (f & (1u << j)) {
                    aq[j].x += wq.x; aq[j].y += wq.y; aq[j].z += wq.z; aq[j].w += wq.w;
                    ak[j].x += wk.x; ak[j].y += wk.y; ak[j].z += wk.z; ak[j].w += wk.w;
                    av[j].x += wv.x; av[j].y += wv.y; av[j].z += wv.z; av[j].w += wv.w;
                }
            }
        }

        #pragma unroll
        for (int j = 0; j < NTQ; j++) {
            size_t rbase = rbase0 + (size_t)j * 16;
            // q
            {
                float y0 = aq[j].x * qs_c.x + qs_h.x, y1 = aq[j].y * qs_c.y + qs_h.y;
                float y2 = aq[j].z * qs_c.z + qs_h.z, y3 = aq[j].w * qs_c.w + qs_h.w;
                uint32_t nib = 0;
                mq[j].x = fmaf(y0 - mq[j].x, 0.5f, mq[j].x); nib |= (mq[j].x >= 1.f) ? 1u : 0u; mq[j].x = (mq[j].x >= 1.f) ? 0.f : mq[j].x;
                mq[j].y = fmaf(y1 - mq[j].y, 0.5f, mq[j].y); nib |= (mq[j].y >= 1.f) ? 2u : 0u; mq[j].y = (mq[j].y >= 1.f) ? 0.f : mq[j].y;
                mq[j].z = fmaf(y2 - mq[j].z, 0.5f, mq[j].z); nib |= (mq[j].z >= 1.f) ? 4u : 0u; mq[j].z = (mq[j].z >= 1.f) ? 0.f : mq[j].z;
                mq[j].w = fmaf(y3 - mq[j].w, 0.5f, mq[j].w); nib |= (mq[j].w >= 1.f) ? 8u : 0u; mq[j].w = (mq[j].w >= 1.f) ? 0.f : mq[j].w;
                store_bits(g_bq + rbase, nib, tid, lane);
            }
            // k
            {
                float y0 = ak[j].x * ks_c.x + ks_h.x, y1 = ak[j].y * ks_c.y + ks_h.y;
                float y2 = ak[j].z * ks_c.z + ks_h.z, y3 = ak[j].w * ks_c.w + ks_h.w;
                uint32_t nib = 0;
                mk[j].x = fmaf(y0 - mk[j].x, 0.5f, mk[j].x); nib |= (mk[j].x >= 1.f) ? 1u : 0u; mk[j].x = (mk[j].x >= 1.f) ? 0.f : mk[j].x;
                mk[j].y = fmaf(y1 - mk[j].y, 0.5f, mk[j].y); nib |= (mk[j].y >= 1.f) ? 2u : 0u; mk[j].y = (mk[j].y >= 1.f) ? 0.f : mk[j].y;
                mk[j].z = fmaf(y2 - mk[j].z, 0.5f, mk[j].z); nib |= (mk[j].z >= 1.f) ? 4u : 0u; mk[j].z = (mk[j].z >= 1.f) ? 0.f : mk[j].z;
                mk[j].w = fmaf(y3 - mk[j].w, 0.5f, mk[j].w); nib |= (mk[j].w >= 1.f) ? 8u : 0u; mk[j].w = (mk[j].w >= 1.f) ? 0.f : mk[j].w;
                store_bits(g_bk + rbase, nib, tid, lane);
            }
            // v
            {
                float y0 = av[j].x * vs_c.x + vs_h.x, y1 = av[j].y * vs_c.y + vs_h.y;
                float y2 = av[j].z * vs_c.z + vs_h.z, y3 = av[j].w * vs_c.w + vs_h.w;
                uint32_t nib = 0;
                mv[j].x = fmaf(y0 - mv[j].x, 0.5f, mv[j].x); nib |= (mv[j].x >= 1.f) ? 1u : 0u; mv[j].x = (mv[j].x >= 1.f) ? 0.f : mv[j].x;
                mv[j].y = fmaf(y1 - mv[j].y, 0.5f, mv[j].y); nib |= (mv[j].y >= 1.f) ? 2u : 0u; mv[j].y = (mv[j].y >= 1.f) ? 0.f : mv[j].y;
                mv[j].z = fmaf(y2 - mv[j].z, 0.5f, mv[j].z); nib |= (mv[j].z >= 1.f) ? 4u : 0u; mv[j].z = (mv[j].z >= 1.f) ? 0.f : mv[j].z;
                mv[j].w = fmaf(y3 - mv[j].w, 0.5f, mv[j].w); nib |= (mv[j].w >= 1.f) ? 8u : 0u; mv[j].w = (mv[j].w >= 1.f) ? 0.f : mv[j].w;
                store_bits(g_bv + rbase, nib, tid, lane);
            }
        }
        __syncthreads();   // protect nmask/list before next t
    }
}

// ---------------------------------------------------------------------------
// 32x32 bit-transpose: g_bk/g_bv [tb][n][c-word] -> g_mk/g_mv [tb][c][n-word]
// ---------------------------------------------------------------------------
__global__ __launch_bounds__(256)
void bit_transpose_kernel()
{
    int wg = blockIdx.x * 8 + (threadIdx.x >> 5);
    int lane = threadIdx.x & 31;
    int tb = wg >> 9;
    int rem = wg & 511;
    int cw = rem >> 5, nw = rem & 31;

    uint32_t wk = g_bk[((size_t)tb * N_ + nw * 32 + lane) * 16 + cw];
    uint32_t wv = g_bv[((size_t)tb * N_ + nw * 32 + lane) * 16 + cw];
    uint32_t myk = 0, myv = 0;
    #pragma unroll
    for (int j = 0; j < 32; j++) {
        uint32_t bk_ = __ballot_sync(FULLW, (wk >> j) & 1u);
        uint32_t bv_ = __ballot_sync(FULLW, (wv >> j) & 1u);
        if (lane == j) { myk = bk_; myv = bv_; }
    }
    g_mk[((size_t)tb * C_ + cw * 32 + lane) * 32 + nw] = myk;
    g_mv[((size_t)tb * C_ + cw * 32 + lane) * 32 + nw] = myv;
}

// ---------------------------------------------------------------------------
// KV[e][dd] = 0.125 * popc-sum(maskK_e & maskV_dd)  per (tb,h) — exact.
// ---------------------------------------------------------------------------
__global__ __launch_bounds__(256)
void kv_popc_kernel()
{
    int idx = blockIdx.x;
    int tb = idx >> 3, h = idx & 7;
    float* KVb = g_kv + (size_t)idx * HD_ * HD_;

    __shared__ uint32_t MK[64][32];
    __shared__ uint32_t MV[64][32];

    int tid = threadIdx.x;
    for (int i = tid; i < 64 * 32; i += 256) {
        int e = i >> 5, w = i & 31;
        MK[e][w] = g_mk[((size_t)tb * C_ + h * HD_ + e) * 32 + w];
        MV[e][w] = g_mv[((size_t)tb * C_ + h * HD_ + e) * 32 + w];
    }
    __syncthreads();

    #pragma unroll
    for (int r = 0; r < 16; r++) {
        int p = r * 256 + tid;
        int e = p >> 6, dd = p & 63;
        int s = 0;
        #pragma unroll
        for (int w = 0; w < 32; w++)
            s += __popc(MK[e][w] & MV[dd][w]);
        KVb[(size_t)e * HD_ + dd] = (float)s * 0.125f;
    }
}

// ---------------------------------------------------------------------------
// FUSED: attention-apply + attn-LIF (vth=0.5) + union proj gather + bias + BN,
// writing FINAL [tb][c][n] layout directly (8-n tile staged in smem).
// Block = (b, n0=8*blockIdx.x), 128 threads; thread owns c=4*tid..3 (head h).
// ---------------------------------------------------------------------------
#define NTP 8

__global__ __launch_bounds__(128)
void attn_proj_lif_kernel(const float* __restrict__ bp,
                          const float* __restrict__ pg, const float* __restrict__ pb,
                          const float* __restrict__ pm, const float* __restrict__ pv,
                          float* __restrict__ out)
{
    int b = blockIdx.y, n0 = blockIdx.x * NTP;
    int tid = threadIdx.x, lane = tid & 31;
    int h = tid >> 4;            // head of this thread's 4 channels
    int q4i = tid & 15;          // float4 index within head row

    __shared__ __align__(16) uint32_t nmask[NTP][16];
    __shared__ __align__(16) uint32_t unionw[16];
    __shared__ __align__(16) uint32_t list32[C_];
    __shared__ int basew[16];
    __shared__ int cnt;
    __shared__ __align__(16) float sout[NTP][C_];   // 16KB transposed-write staging

    const float4* Wp4 = (const float4*)(g_wt + 3 * (size_t)CC);

    float4 sc, sh;
    {
        float4 g = ((const float4*)pg)[tid], bb = ((const float4*)pb)[tid];
        float4 m = ((const float4*)pm)[tid], v = ((const float4*)pv)[tid];
        float4 bi = ((const float4*)bp)[tid];
        sc.x = g.x * rsqrtf(v.x + EPS_); sh.x = bb.x + (bi.x - m.x) * sc.x;
        sc.y = g.y * rsqrtf(v.y + EPS_); sh.y = bb.y + (bi.y - m.y) * sc.y;
        sc.z = g.z * rsqrtf(v.z + EPS_); sh.z = bb.z + (bi.z - m.z) * sc.z;
        sc.w = g.w * rsqrtf(v.w + EPS_); sh.w = bb.w + (bi.w - m.w) * sc.w;
    }

    float4 mo[NTP];
    #pragma unroll
    for (int j = 0; j < NTP; j++) mo[j] = make_float4(0.f, 0.f, 0.f, 0.f);

    for (int t = 0; t < T_; t++) {
        int tb = t * B_ + b;
        size_t rbase0 = ((size_t)tb * N_ + n0) * 16;
        const float4* KVb = (const float4*)(g_kv + (size_t)(tb * NH_ + h) * HD_ * HD_);

        // ---- per-n: attention apply + LIF -> nibble -> nmask[j] ----
        #pragma unroll
        for (int j = 0; j < NTP; j++) {
            uint32_t qw0 = g_bq[rbase0 + (size_t)j * 16 + 2 * h];
            uint32_t qw1 = g_bq[rbase0 + (size_t)j * 16 + 2 * h + 1];

            float4 a = make_float4(0.f, 0.f, 0.f, 0.f);
            uint32_t m = qw0;
            while (m) {
                int e = __ffs(m) - 1; m &= m - 1;
                float4 kvv = KVb[e * 16 + q4i];
                a.x += kvv.x; a.y += kvv.y; a.z += kvv.z; a.w += kvv.w;
            }
            m = qw1;
            while (m) {
                int e = __ffs(m) - 1; m &= m - 1;
                float4 kvv = KVb[(32 + e) * 16 + q4i];
                a.x += kvv.x; a.y += kvv.y; a.z += kvv.z; a.w += kvv.w;
            }

            uint32_t nib = 0;
            mo[j].x = fmaf(a.x - mo[j].x, 0.5f, mo[j].x); nib |= (mo[j].x >= 0.5f) ? 1u : 0u; mo[j].x = (mo[j].x >= 0.5f) ? 0.f : mo[j].x;
            mo[j].y = fmaf(a.y - mo[j].y, 0.5f, mo[j].y); nib |= (mo[j].y >= 0.5f) ? 2u : 0u; mo[j].y = (mo[j].y >= 0.5f) ? 0.f : mo[j].y;
            mo[j].z = fmaf(a.z - mo[j].z, 0.5f, mo[j].z); nib |= (mo[j].z >= 0.5f) ? 4u : 0u; mo[j].z = (mo[j].z >= 0.5f) ? 0.f : mo[j].z;
            mo[j].w = fmaf(a.w - mo[j].w, 0.5f, mo[j].w); nib |= (mo[j].w >= 0.5f) ? 8u : 0u; mo[j].w = (mo[j].w >= 0.5f) ? 0.f : mo[j].w;

            uint32_t contrib = nib << (4 * (lane & 7));
            contrib |= __shfl_xor_sync(FULLW, contrib, 1);
            contrib |= __shfl_xor_sync(FULLW, contrib, 2);
            contrib |= __shfl_xor_sync(FULLW, contrib, 4);
            if ((lane & 7) == 0) nmask[j][tid >> 3] = contrib;
        }
        __syncthreads();

        int count = decode_union<NTP>(nmask, unionw, list32, basew, &cnt);

        // ---- union projection gather ----
        float4 ap[NTP];
        #pragma unroll
        for (int j = 0; j < NTP; j++) ap[j] = make_float4(0.f, 0.f, 0.f, 0.f);

        for (int i = 0; i < count; i++) {
            uint32_t e = list32[i];
            int c = e & 0xffff;
            uint32_t f = e >> 16;
            float4 wp = Wp4[(size_t)c * 128 + tid];
            #pragma unroll
            for (int j = 0; j < NTP; j++) {
                if (f & (1u << j)) {
                    ap[j].x += wp.x; ap[j].y += wp.y; ap[j].z += wp.z; ap[j].w += wp.w;
                }
            }
        }

        // ---- BN epilogue, stage per-n rows in smem ----
        #pragma unroll
        for (int j = 0; j < NTP; j++) {
            float4 o;
            o.x = ap[j].x * sc.x + sh.x;
            o.y = ap[j].y * sc.y + sh.y;
            o.z = ap[j].z * sc.z + sh.z;
            o.w = ap[j].w * sc.w + sh.w;
            ((float4*)sout[j])[tid] = o;
        }
        __syncthreads();

        // ---- transposed write: out[tb][c][n0..n0+7] (two float4 per c) ----
        float* ob = out + (size_t)tb * C_ * N_ + n0;
        for (int c = tid; c < C_; c += 128) {
            float4 w0, w1;
            w0.x = sout[0][c]; w0.y = sout[1][c]; w0.z = sout[2][c]; w0.w = sout[3][c];
            w1.x = sout[4][c]; w1.y = sout[5][c]; w1.z = sout[6][c]; w1.w = sout[7][c];
            *reinterpret_cast<float4*>(ob + (size_t)c * N_) = w0;
            *reinterpret_cast<float4*>(ob + (size_t)c * N_ + 4) = w1;
        }
        __syncthreads();   // protect smem before next t
    }
}

// ---------------------------------------------------------------------------
// Launch
// ---------------------------------------------------------------------------
extern "C" void kernel_launch(void* const* d_in, const int* in_sizes, int n_in,
                              void* d_out, int out_size)
{
    const float* x   = (const float*)d_in[0];
    const float* Wq  = (const float*)d_in[1];
    const float* q_g = (const float*)d_in[2];
    const float* q_b = (const float*)d_in[3];
    const float* q_m = (const float*)d_in[4];
    const float* q_v = (const float*)d_in[5];
    const float* Wk  = (const float*)d_in[6];
    const float* k_g = (const float*)d_in[7];
    const float* k_b = (const float*)d_in[8];
    const float* k_m = (const float*)d_in[9];
    const float* k_v = (const float*)d_in[10];
    const float* Wv  = (const float*)d_in[11];
    const float* v_g = (const float*)d_in[12];
    const float* v_b = (const float*)d_in[13];
    const float* v_m = (const float*)d_in[14];
    const float* v_v = (const float*)d_in[15];
    const float* Wp  = (const float*)d_in[16];
    const float* bp  = (const float*)d_in[17];
    const float* p_g = (const float*)d_in[18];
    const float* p_b = (const float*)d_in[19];
    const float* p_m = (const float*)d_in[20];
    const float* p_v = (const float*)d_in[21];
    float* out = (float*)d_out;

    prep_wt_kernel<<<dim3(C_ / 32, C_ / 32, 4), 256>>>(Wq, Wk, Wv, Wp);
    lif_in_bits_kernel<<<dim3(N_ / 32, C_ / 32, B_), 256>>>(x);
    gather_qkv_lif_kernel<<<dim3(N_ / NTQ, B_), 128>>>(
        q_g, q_b, q_m, q_v, k_g, k_b, k_m, k_v, v_g, v_b, v_m, v_v);
    bit_transpose_kernel<<<TBAT * 512 / 8, 256>>>();
    kv_popc_kernel<<<TBAT * NH_, 256>>>();
    attn_proj_lif_kernel<<<dim3(N_ / NTP, B_), 128>>>(bp, p_g, p_b, p_m, p_v, out);
}

// round 15
// speedup vs baseline: 1.0849x; 1.0849x over previous
#include <cuda_runtime.h>
#include <cstdint>

// ---------------------------------------------------------------------------
// Problem constants
// ---------------------------------------------------------------------------
#define T_  4
#define B_  4
#define C_  512
#define N_  1024          // H*W
#define NH_ 8
#define HD_ 64
#define TBAT (T_*B_)
#define BCN  (B_*C_*N_)
#define CC   (C_*C_)
#define EPS_ 1e-5f
#define FULLW 0xffffffffu

// ---------------------------------------------------------------------------
// Device scratch (static — no allocation anywhere)
// Spikes live as bitmasks: row layout [tb][n][16 c-words] (bit = c&31).
// ---------------------------------------------------------------------------
__device__ float    g_wt[4 * CC];          // W^T per branch: [w][c][d]
__device__ uint32_t g_bx[TBAT * N_ * 16];  // input spike bits
__device__ uint32_t g_bq[TBAT * N_ * 16];  // q spike bits
__device__ uint32_t g_bk[TBAT * N_ * 16];  // k spike bits
__device__ uint32_t g_bv[TBAT * N_ * 16];  // v spike bits
__device__ uint32_t g_mk[TBAT * C_ * 32];  // k bits reoriented: [tb][c][32 n-words]
__device__ uint32_t g_mv[TBAT * C_ * 32];
__device__ float    g_ot[T_ * BCN];        // proj output [tb][n][c]
__device__ float    g_kv[TBAT * NH_ * HD_ * HD_];  // [tb*8+h][e][dd], carries x0.125

// ---------------------------------------------------------------------------
// Weight transpose (all 4 branches): W[d][c] -> g_wt[w][c][d]
// ---------------------------------------------------------------------------
__global__ __launch_bounds__(256)
void prep_wt_kernel(const float* __restrict__ Wq, const float* __restrict__ Wk,
                    const float* __restrict__ Wv, const float* __restrict__ Wp)
{
    int w = blockIdx.z;
    const float* src = (w == 0) ? Wq : (w == 1) ? Wk : (w == 2) ? Wv : Wp;
    float* dst = g_wt + (size_t)w * CC;
    int d0 = blockIdx.y * 32, c0 = blockIdx.x * 32;
    int tx = threadIdx.x & 31, ty = threadIdx.x >> 5;
    __shared__ float s[32][33];
    #pragma unroll
    for (int r = 0; r < 4; r++)
        s[ty + 8 * r][tx] = src[(size_t)(d0 + ty + 8 * r) * C_ + c0 + tx];
    __syncthreads();
    #pragma unroll
    for (int r = 0; r < 4; r++)
        dst[(size_t)(c0 + ty + 8 * r) * C_ + d0 + tx] = s[tx][ty + 8 * r];
}

// ---------------------------------------------------------------------------
// Input LIF -> spike BITS, float4-widened over n.
// Tile: (b, 32 c) x (128 n). 256 threads; thread handles 4 c-rows x 4 n.
// ---------------------------------------------------------------------------
__global__ __launch_bounds__(256)
void lif_in_bits_kernel(const float* __restrict__ x)
{
    int b  = blockIdx.z;
    int c0 = blockIdx.y * 32;
    int n0 = blockIdx.x * 128;
    int warp = threadIdx.x >> 5, lane = threadIdx.x & 31;

    __shared__ float s[32][128];
    // membranes: 4 c-rows (r) x 4 n (inside float4)
    float4 v[4];
    #pragma unroll
    for (int r = 0; r < 4; r++) v[r] = make_float4(0.f, 0.f, 0.f, 0.f);

    for (int t = 0; t < T_; t++) {
        int tb = t * B_ + b;
        #pragma unroll
        for (int r = 0; r < 4; r++) {
            int c = c0 + warp + 8 * r;
            float4 xv = *reinterpret_cast<const float4*>(
                x + (((size_t)tb) * C_ + c) * (size_t)N_ + n0 + lane * 4);
            float4 sp;
            v[r].x = fmaf(xv.x - v[r].x, 0.5f, v[r].x); sp.x = (v[r].x >= 1.f) ? 1.f : 0.f; v[r].x = (v[r].x >= 1.f) ? 0.f : v[r].x;
            v[r].y = fmaf(xv.y - v[r].y, 0.5f, v[r].y); sp.y = (v[r].y >= 1.f) ? 1.f : 0.f; v[r].y = (v[r].y >= 1.f) ? 0.f : v[r].y;
            v[r].z = fmaf(xv.z - v[r].z, 0.5f, v[r].z); sp.z = (v[r].z >= 1.f) ? 1.f : 0.f; v[r].z = (v[r].z >= 1.f) ? 0.f : v[r].z;
            v[r].w = fmaf(xv.w - v[r].w, 0.5f, v[r].w); sp.w = (v[r].w >= 1.f) ? 1.f : 0.f; v[r].w = (v[r].w >= 1.f) ? 0.f : v[r].w;
            s[warp + 8 * r][lane * 4 + 0] = sp.x;
            s[warp + 8 * r][lane * 4 + 1] = sp.y;
            s[warp + 8 * r][lane * 4 + 2] = sp.z;
            s[warp + 8 * r][lane * 4 + 3] = sp.w;
        }
        __syncthreads();
        // ballots: warp w handles n = n0 + w*16 + r (16 n's per warp)
        #pragma unroll
        for (int r = 0; r < 16; r++) {
            int nl = warp * 16 + r;
            uint32_t word = __ballot_sync(FULLW, s[lane][nl] != 0.f);
            if (lane == 0)
                g_bx[((size_t)tb * N_ + n0 + nl) * 16 + (c0 >> 5)] = word;
        }
        __syncthreads();
    }
}

// ---------------------------------------------------------------------------
// List decode from 16 mask words (deterministic, ascending c). 128 threads.
// ---------------------------------------------------------------------------
__device__ __forceinline__ int decode_list(const uint32_t* __restrict__ gmask,
                                           uint16_t* list, uint32_t* maskw,
                                           int* basew, int* cntp)
{
    int tid = threadIdx.x, warp = tid >> 5, lane = tid & 31;
    if (tid < 16) maskw[tid] = gmask[tid];
    __syncthreads();
    if (tid == 0) {
        int s = 0;
        #pragma unroll
        for (int ci = 0; ci < 16; ci++) { basew[ci] = s; s += __popc(maskw[ci]); }
        *cntp = s;
    }
    __syncthreads();
    #pragma unroll
    for (int ci = warp; ci < 16; ci += 4) {
        uint32_t m = maskw[ci];
        if (m & (1u << lane))
            list[basew[ci] + __popc(m & ((1u << lane) - 1u))] = (uint16_t)(ci * 32 + lane);
    }
    __syncthreads();
    return *cntp;
}

// ---------------------------------------------------------------------------
// Pack 4 spike bits/thread into 16 words across 128 threads, store to gmem.
// ---------------------------------------------------------------------------
__device__ __forceinline__ void store_bits(uint32_t* __restrict__ grow,
                                           uint32_t nib, int tid, int lane)
{
    uint32_t contrib = nib << (4 * (lane & 7));
    contrib |= __shfl_xor_sync(FULLW, contrib, 1);
    contrib |= __shfl_xor_sync(FULLW, contrib, 2);
    contrib |= __shfl_xor_sync(FULLW, contrib, 4);
    if ((lane & 7) == 0) grow[tid >> 3] = contrib;
}

// ---------------------------------------------------------------------------
// Fused Q/K/V gather-GEMM + BN + LIF (vth=1) -> spike BITS.  (R12 version)
// Block = (b, n); loops t with LIF state in registers.
// ---------------------------------------------------------------------------
__global__ __launch_bounds__(128)
void gather_qkv_lif_kernel(const float* __restrict__ qg, const float* __restrict__ qb,
                           const float* __restrict__ qm, const float* __restrict__ qv,
                           const float* __restrict__ kg, const float* __restrict__ kb,
                           const float* __restrict__ km, const float* __restrict__ kv,
                           const float* __restrict__ vg, const float* __restrict__ vb,
                           const float* __restrict__ vm, const float* __restrict__ vv)
{
    int b = blockIdx.y, n = blockIdx.x;
    int tid = threadIdx.x, lane = tid & 31;

    __shared__ uint16_t list[C_];
    __shared__ uint32_t maskw[16];
    __shared__ int basew[16];
    __shared__ int cnt;

    const float4* Wq4 = (const float4*)(g_wt + 0 * (size_t)CC);
    const float4* Wk4 = (const float4*)(g_wt + 1 * (size_t)CC);
    const float4* Wv4 = (const float4*)(g_wt + 2 * (size_t)CC);

    float4 qs_c, qs_h, ks_c, ks_h, vs_c, vs_h;
    {
        float4 g = ((const float4*)qg)[tid], bb = ((const float4*)qb)[tid];
        float4 m = ((const float4*)qm)[tid], v = ((const float4*)qv)[tid];
        qs_c.x = g.x * rsqrtf(v.x + EPS_); qs_h.x = bb.x - m.x * qs_c.x;
        qs_c.y = g.y * rsqrtf(v.y + EPS_); qs_h.y = bb.y - m.y * qs_c.y;
        qs_c.z = g.z * rsqrtf(v.z + EPS_); qs_h.z = bb.z - m.z * qs_c.z;
        qs_c.w = g.w * rsqrtf(v.w + EPS_); qs_h.w = bb.w - m.w * qs_c.w;
    }
    {
        float4 g = ((const float4*)kg)[tid], bb = ((const float4*)kb)[tid];
        float4 m = ((const float4*)km)[tid], v = ((const float4*)kv)[tid];
        ks_c.x = g.x * rsqrtf(v.x + EPS_); ks_h.x = bb.x - m.x * ks_c.x;
        ks_c.y = g.y * rsqrtf(v.y + EPS_); ks_h.y = bb.y - m.y * ks_c.y;
        ks_c.z = g.z * rsqrtf(v.z + EPS_); ks_h.z = bb.z - m.z * ks_c.z;
        ks_c.w = g.w * rsqrtf(v.w + EPS_); ks_h.w = bb.w - m.w * ks_c.w;
    }
    {
        float4 g = ((const float4*)vg)[tid], bb = ((const float4*)vb)[tid];
        float4 m = ((const float4*)vm)[tid], v = ((const float4*)vv)[tid];
        vs_c.x = g.x * rsqrtf(v.x + EPS_); vs_h.x = bb.x - m.x * vs_c.x;
        vs_c.y = g.y * rsqrtf(v.y + EPS_); vs_h.y = bb.y - m.y * vs_c.y;
        vs_c.z = g.z * rsqrtf(v.z + EPS_); vs_h.z = bb.z - m.z * vs_c.z;
        vs_c.w = g.w * rsqrtf(v.w + EPS_); vs_h.w = bb.w - m.w * vs_c.w;
    }

    float4 mq = {0.f,0.f,0.f,0.f}, mk = mq, mv = mq;

    for (int t = 0; t < T_; t++) {
        int tb = t * B_ + b;
        size_t rbase = ((size_t)tb * N_ + n) * 16;
        int count = decode_list(g_bx + rbase, list, maskw, basew, &cnt);

        float4 aq = {0.f,0.f,0.f,0.f}, ak = aq, av = aq;
        for (int i = 0; i < count; i++) {
            int c = list[i];
            float4 wq = Wq4[(size_t)c * 128 + tid];
            float4 wk = Wk4[(size_t)c * 128 + tid];
            float4 wv = Wv4[(size_t)c * 128 + tid];
            aq.x += wq.x; aq.y += wq.y; aq.z += wq.z; aq.w += wq.w;
            ak.x += wk.x; ak.y += wk.y; ak.z += wk.z; ak.w += wk.w;
            av.x += wv.x; av.y += wv.y; av.z += wv.z; av.w += wv.w;
        }

        {
            float y0 = aq.x * qs_c.x + qs_h.x, y1 = aq.y * qs_c.y + qs_h.y;
            float y2 = aq.z * qs_c.z + qs_h.z, y3 = aq.w * qs_c.w + qs_h.w;
            uint32_t nib = 0;
            mq.x = fmaf(y0 - mq.x, 0.5f, mq.x); nib |= (mq.x >= 1.f) ? 1u : 0u; mq.x = (mq.x >= 1.f) ? 0.f : mq.x;
            mq.y = fmaf(y1 - mq.y, 0.5f, mq.y); nib |= (mq.y >= 1.f) ? 2u : 0u; mq.y = (mq.y >= 1.f) ? 0.f : mq.y;
            mq.z = fmaf(y2 - mq.z, 0.5f, mq.z); nib |= (mq.z >= 1.f) ? 4u : 0u; mq.z = (mq.z >= 1.f) ? 0.f : mq.z;
            mq.w = fmaf(y3 - mq.w, 0.5f, mq.w); nib |= (mq.w >= 1.f) ? 8u : 0u; mq.w = (mq.w >= 1.f) ? 0.f : mq.w;
            store_bits(g_bq + rbase, nib, tid, lane);
        }
        {
            float y0 = ak.x * ks_c.x + ks_h.x, y1 = ak.y * ks_c.y + ks_h.y;
            float y2 = ak.z * ks_c.z + ks_h.z, y3 = ak.w * ks_c.w + ks_h.w;
            uint32_t nib = 0;
            mk.x = fmaf(y0 - mk.x, 0.5f, mk.x); nib |= (mk.x >= 1.f) ? 1u : 0u; mk.x = (mk.x >= 1.f) ? 0.f : mk.x;
            mk.y = fmaf(y1 - mk.y, 0.5f, mk.y); nib |= (mk.y >= 1.f) ? 2u : 0u; mk.y = (mk.y >= 1.f) ? 0.f : mk.y;
            mk.z = fmaf(y2 - mk.z, 0.5f, mk.z); nib |= (mk.z >= 1.f) ? 4u : 0u; mk.z = (mk.z >= 1.f) ? 0.f : mk.z;
            mk.w = fmaf(y3 - mk.w, 0.5f, mk.w); nib |= (mk.w >= 1.f) ? 8u : 0u; mk.w = (mk.w >= 1.f) ? 0.f : mk.w;
            store_bits(g_bk + rbase, nib, tid, lane);
        }
        {
            float y0 = av.x * vs_c.x + vs_h.x, y1 = av.y * vs_c.y + vs_h.y;
            float y2 = av.z * vs_c.z + vs_h.z, y3 = av.w * vs_c.w + vs_h.w;
            uint32_t nib = 0;
            mv.x = fmaf(y0 - mv.x, 0.5f, mv.x); nib |= (mv.x >= 1.f) ? 1u : 0u; mv.x = (mv.x >= 1.f) ? 0.f : mv.x;
            mv.y = fmaf(y1 - mv.y, 0.5f, mv.y); nib |= (mv.y >= 1.f) ? 2u : 0u; mv.y = (mv.y >= 1.f) ? 0.f : mv.y;
            mv.z = fmaf(y2 - mv.z, 0.5f, mv.z); nib |= (mv.z >= 1.f) ? 4u : 0u; mv.z = (mv.z >= 1.f) ? 0.f : mv.z;
            mv.w = fmaf(y3 - mv.w, 0.5f, mv.w); nib |= (mv.w >= 1.f) ? 8u : 0u; mv.w = (mv.w >= 1.f) ? 0.f : mv.w;
            store_bits(g_bv + rbase, nib, tid, lane);
        }
    }
}

// ---------------------------------------------------------------------------
// 32x32 bit-transpose: g_bk/g_bv [tb][n][c-word] -> g_mk/g_mv [tb][c][n-word]
// ---------------------------------------------------------------------------
__global__ __launch_bounds__(256)
void bit_transpose_kernel()
{
    int wg = blockIdx.x * 8 + (threadIdx.x >> 5);
    int lane = threadIdx.x & 31;
    int tb = wg >> 9;
    int rem = wg & 511;
    int cw = rem >> 5, nw = rem & 31;

    uint32_t wk = g_bk[((size_t)tb * N_ + nw * 32 + lane) * 16 + cw];
    uint32_t wv = g_bv[((size_t)tb * N_ + nw * 32 + lane) * 16 + cw];
    uint32_t myk = 0, myv = 0;
    #pragma unroll
    for (int j = 0; j < 32; j++) {
        uint32_t bk_ = __ballot_sync(FULLW, (wk >> j) & 1u);
        uint32_t bv_ = __ballot_sync(FULLW, (wv >> j) & 1u);
        if (lane == j) { myk = bk_; myv = bv_; }
    }
    g_mk[((size_t)tb * C_ + cw * 32 + lane) * 32 + nw] = myk;
    g_mv[((size_t)tb * C_ + cw * 32 + lane) * 32 + nw] = myv;
}

// ---------------------------------------------------------------------------
// KV[e][dd] = 0.125 * popc-sum(maskK_e & maskV_dd)  per (tb,h) — exact.
// ---------------------------------------------------------------------------
__global__ __launch_bounds__(256)
void kv_popc_kernel()
{
    int idx = blockIdx.x;
    int tb = idx >> 3, h = idx & 7;
    float* KVb = g_kv + (size_t)idx * HD_ * HD_;

    __shared__ uint32_t MK[64][32];
    __shared__ uint32_t MV[64][32];

    int tid = threadIdx.x;
    for (int i = tid; i < 64 * 32; i += 256) {
        int e = i >> 5, w = i & 31;
        MK[e][w] = g_mk[((size_t)tb * C_ + h * HD_ + e) * 32 + w];
        MV[e][w] = g_mv[((size_t)tb * C_ + h * HD_ + e) * 32 + w];
    }
    __syncthreads();

    #pragma unroll
    for (int r = 0; r < 16; r++) {
        int p = r * 256 + tid;
        int e = p >> 6, dd = p & 63;
        int s = 0;
        #pragma unroll
        for (int w = 0; w < 32; w++)
            s += __popc(MK[e][w] & MV[dd][w]);
        KVb[(size_t)e * HD_ + dd] = (float)s * 0.125f;
    }
}

// ---------------------------------------------------------------------------
// FUSED: attention-apply + attn-LIF (vth=0.5) + projection gather + bias + BN.
// (R12 version: block = (b, n), loops t; writes g_ot [tb][n][c] coalesced.)
// ---------------------------------------------------------------------------
__global__ __launch_bounds__(128)
void attn_proj_lif_kernel(const float* __restrict__ bp,
                          const float* __restrict__ pg, const float* __restrict__ pb,
                          const float* __restrict__ pm, const float* __restrict__ pv)
{
    int b = blockIdx.y, n = blockIdx.x;
    int tid = threadIdx.x, warp = tid >> 5, lane = tid & 31;
    int h = tid >> 4;
    int q4i = tid & 15;

    __shared__ uint16_t list[C_];
    __shared__ uint32_t maskw[16];
    __shared__ int basew[16];
    __shared__ int cnt;

    const float4* Wp4 = (const float4*)(g_wt + 3 * (size_t)CC);

    float4 sc, sh;
    {
        float4 g = ((const float4*)pg)[tid], bb = ((const float4*)pb)[tid];
        float4 m = ((const float4*)pm)[tid], v = ((const float4*)pv)[tid];
        float4 bi = ((const float4*)bp)[tid];
        sc.x = g.x * rsqrtf(v.x + EPS_); sh.x = bb.x + (bi.x - m.x) * sc.x;
        sc.y = g.y * rsqrtf(v.y + EPS_); sh.y = bb.y + (bi.y - m.y) * sc.y;
        sc.z = g.z * rsqrtf(v.z + EPS_); sh.z = bb.z + (bi.z - m.z) * sc.z;
        sc.w = g.w * rsqrtf(v.w + EPS_); sh.w = bb.w + (bi.w - m.w) * sc.w;
    }

    float4 mo = {0.f, 0.f, 0.f, 0.f};

    for (int t = 0; t < T_; t++) {
        int tb = t * B_ + b;
        size_t rbase = ((size_t)tb * N_ + n) * 16;

        uint32_t qw0 = g_bq[rbase + 2 * h];
        uint32_t qw1 = g_bq[rbase + 2 * h + 1];
        const float4* KVb = (const float4*)(g_kv + (size_t)(tb * NH_ + h) * HD_ * HD_);

        float4 a = {0.f, 0.f, 0.f, 0.f};
        uint32_t m = qw0;
        while (m) {
            int e = __ffs(m) - 1; m &= m - 1;
            float4 kvv = KVb[e * 16 + q4i];
            a.x += kvv.x; a.y += kvv.y; a.z += kvv.z; a.w += kvv.w;
        }
        m = qw1;
        while (m) {
            int e = __ffs(m) - 1; m &= m - 1;
            float4 kvv = KVb[(32 + e) * 16 + q4i];
            a.x += kvv.x; a.y += kvv.y; a.z += kvv.z; a.w += kvv.w;
        }

        uint32_t nib = 0;
        mo.x = fmaf(a.x - mo.x, 0.5f, mo.x); nib |= (mo.x >= 0.5f) ? 1u : 0u; mo.x = (mo.x >= 0.5f) ? 0.f : mo.x;
        mo.y = fmaf(a.y - mo.y, 0.5f, mo.y); nib |= (mo.y >= 0.5f) ? 2u : 0u; mo.y = (mo.y >= 0.5f) ? 0.f : mo.y;
        mo.z = fmaf(a.z - mo.z, 0.5f, mo.z); nib |= (mo.z >= 0.5f) ? 4u : 0u; mo.z = (mo.z >= 0.5f) ? 0.f : mo.z;
        mo.w = fmaf(a.w - mo.w, 0.5f, mo.w); nib |= (mo.w >= 0.5f) ? 8u : 0u; mo.w = (mo.w >= 0.5f) ? 0.f : mo.w;

        uint32_t contrib = nib << (4 * (lane & 7));
        contrib |= __shfl_xor_sync(FULLW, contrib, 1);
        contrib |= __shfl_xor_sync(FULLW, contrib, 2);
        contrib |= __shfl_xor_sync(FULLW, contrib, 4);
        if ((lane & 7) == 0) maskw[tid >> 3] = contrib;
        __syncthreads();

        if (tid == 0) {
            int s = 0;
            #pragma unroll
            for (int ci = 0; ci < 16; ci++) { basew[ci] = s; s += __popc(maskw[ci]); }
            cnt = s;
        }
        __syncthreads();
        #pragma unroll
        for (int ci = warp; ci < 16; ci += 4) {
            uint32_t mm = maskw[ci];
            if (mm & (1u << lane))
                list[basew[ci] + __popc(mm & ((1u << lane) - 1u))] = (uint16_t)(ci * 32 + lane);
        }
        __syncthreads();
        int count = cnt;

        float4 ap = {0.f, 0.f, 0.f, 0.f};
        for (int i = 0; i < count; i++) {
            int c = list[i];
            float4 wp = Wp4[(size_t)c * 128 + tid];
            ap.x += wp.x; ap.y += wp.y; ap.z += wp.z; ap.w += wp.w;
        }

        float4 o;
        o.x = ap.x * sc.x + sh.x;
        o.y = ap.y * sc.y + sh.y;
        o.z = ap.z * sc.z + sh.z;
        o.w = ap.w * sc.w + sh.w;
        ((float4*)(g_ot + ((size_t)tb * N_ + n) * C_))[tid] = o;
        __syncthreads();
    }
}

// ---------------------------------------------------------------------------
// Final transpose: g_ot [tb][n][c] -> out [tb][c][n], float4-widened.
// Tile: 32 n x 128 c. Read float4 over c; write float4 over n (via smem).
// ---------------------------------------------------------------------------
__global__ __launch_bounds__(256)
void transpose_out_kernel(float* __restrict__ out)
{
    int tb = blockIdx.z;
    int n0 = blockIdx.y * 32;
    int c0 = blockIdx.x * 128;
    int tid = threadIdx.x;

    __shared__ __align__(16) float s[32][129];

    const float* src = g_ot + (size_t)tb * N_ * C_;
    float* dst = out + (size_t)tb * C_ * N_;

    // read: 32 n-rows x 128 c = 1024 float4; thread reads 4 (n = tid>>3 group)
    {
        int nr = tid >> 3, cq = tid & 7;      // nr 0..31, cq 0..7 (16 floats each)
        #pragma unroll
        for (int r = 0; r < 4; r++) {
            float4 vv = *reinterpret_cast<const float4*>(
                src + (size_t)(n0 + nr) * C_ + c0 + cq * 16 + r * 4);
            s[nr][cq * 16 + r * 4 + 0] = vv.x;
            s[nr][cq * 16 + r * 4 + 1] = vv.y;
            s[nr][cq * 16 + r * 4 + 2] = vv.z;
            s[nr][cq * 16 + r * 4 + 3] = vv.w;
        }
    }
    __syncthreads();

    // write: 128 c-rows x 32 n = 1024 float4; thread writes 4
    {
        int cr = tid >> 1, nq = tid & 1;      // cr 0..127, nq 0..1 (16 floats each)
        #pragma unroll
        for (int r = 0; r < 4; r++) {
            int nn = nq * 16 + r * 4;
            float4 vv;
            vv.x = s[nn + 0][cr];
            vv.y = s[nn + 1][cr];
            vv.z = s[nn + 2][cr];
            vv.w = s[nn + 3][cr];
            *reinterpret_cast<float4*>(dst + (size_t)(c0 + cr) * N_ + n0 + nn) = vv;
        }
    }
}

// ---------------------------------------------------------------------------
// Launch
// ---------------------------------------------------------------------------
extern "C" void kernel_launch(void* const* d_in, const int* in_sizes, int n_in,
                              void* d_out, int out_size)
{
    const float* x   = (const float*)d_in[0];
    const float* Wq  = (const float*)d_in[1];
    const float* q_g = (const float*)d_in[2];
    const float* q_b = (const float*)d_in[3];
    const float* q_m = (const float*)d_in[4];
    const float* q_v = (const float*)d_in[5];
    const float* Wk  = (const float*)d_in[6];
    const float* k_g = (const float*)d_in[7];
    const float* k_b = (const float*)d_in[8];
    const float* k_m = (const float*)d_in[9];
    const float* k_v = (const float*)d_in[10];
    const float* Wv  = (const float*)d_in[11];
    const float* v_g = (const float*)d_in[12];
    const float* v_b = (const float*)d_in[13];
    const float* v_m = (const float*)d_in[14];
    const float* v_v = (const float*)d_in[15];
    const float* Wp  = (const float*)d_in[16];
    const float* bp  = (const float*)d_in[17];
    const float* p_g = (const float*)d_in[18];
    const float* p_b = (const float*)d_in[19];
    const float* p_m = (const float*)d_in[20];
    const float* p_v = (const float*)d_in[21];
    float* out = (float*)d_out;

    prep_wt_kernel<<<dim3(C_ / 32, C_ / 32, 4), 256>>>(Wq, Wk, Wv, Wp);
    lif_in_bits_kernel<<<dim3(N_ / 128, C_ / 32, B_), 256>>>(x);
    gather_qkv_lif_kernel<<<dim3(N_, B_), 128>>>(
        q_g, q_b, q_m, q_v, k_g, k_b, k_m, k_v, v_g, v_b, v_m, v_v);
    bit_transpose_kernel<<<TBAT * 512 / 8, 256>>>();
    kv_popc_kernel<<<TBAT * NH_, 256>>>();
    attn_proj_lif_kernel<<<dim3(N_, B_), 128>>>(bp, p_g, p_b, p_m, p_v);
    transpose_out_kernel<<<dim3(C_ / 128, N_ / 32, TBAT), 256>>>(out);
}

// round 16
// speedup vs baseline: 1.2396x; 1.1425x over previous
#include <cuda_runtime.h>
#include <cstdint>

// ---------------------------------------------------------------------------
// Problem constants
// ---------------------------------------------------------------------------
#define T_  4
#define B_  4
#define C_  512
#define N_  1024          // H*W
#define NH_ 8
#define HD_ 64
#define TBAT (T_*B_)
#define BCN  (B_*C_*N_)
#define CC   (C_*C_)
#define EPS_ 1e-5f
#define FULLW 0xffffffffu

// ---------------------------------------------------------------------------
// Device scratch (static — no allocation anywhere)
// Spikes live as bitmasks: row layout [tb][n][16 c-words] (bit = c&31).
// ---------------------------------------------------------------------------
__device__ float    g_wt[4 * CC];          // W^T per branch: [w][c][d]
__device__ uint32_t g_bx[TBAT * N_ * 16];  // input spike bits
__device__ uint32_t g_bq[TBAT * N_ * 16];  // q spike bits
__device__ uint32_t g_bk[TBAT * N_ * 16];  // k spike bits
__device__ uint32_t g_bv[TBAT * N_ * 16];  // v spike bits
__device__ float    g_ot[T_ * BCN];        // proj output [tb][n][c]
__device__ float    g_kv[TBAT * NH_ * HD_ * HD_];  // [tb*8+h][e][dd], carries x0.125

// ---------------------------------------------------------------------------
// Weight transpose (all 4 branches): W[d][c] -> g_wt[w][c][d]
// ---------------------------------------------------------------------------
__global__ __launch_bounds__(256)
void prep_wt_kernel(const float* __restrict__ Wq, const float* __restrict__ Wk,
                    const float* __restrict__ Wv, const float* __restrict__ Wp)
{
    int w = blockIdx.z;
    const float* src = (w == 0) ? Wq : (w == 1) ? Wk : (w == 2) ? Wv : Wp;
    float* dst = g_wt + (size_t)w * CC;
    int d0 = blockIdx.y * 32, c0 = blockIdx.x * 32;
    int tx = threadIdx.x & 31, ty = threadIdx.x >> 5;
    __shared__ float s[32][33];
    #pragma unroll
    for (int r = 0; r < 4; r++)
        s[ty + 8 * r][tx] = src[(size_t)(d0 + ty + 8 * r) * C_ + c0 + tx];
    __syncthreads();
    #pragma unroll
    for (int r = 0; r < 4; r++)
        dst[(size_t)(c0 + ty + 8 * r) * C_ + d0 + tx] = s[tx][ty + 8 * r];
}

// ---------------------------------------------------------------------------
// Input LIF -> spike BITS.  x fp32 [t,b,c,n] -> g_bx[tb][n][c-word], vth=1.
// (R12 version: 32x33-padded smem, conflict-free ballots.)
// ---------------------------------------------------------------------------
__global__ __launch_bounds__(256)
void lif_in_bits_kernel(const float* __restrict__ x)
{
    int b  = blockIdx.z;
    int c0 = blockIdx.y * 32;
    int n0 = blockIdx.x * 32;
    int tx = threadIdx.x & 31, ty = threadIdx.x >> 5;
    int warp = threadIdx.x >> 5, lane = threadIdx.x & 31;
    __shared__ float s[32][33];
    float v[4] = {0.f, 0.f, 0.f, 0.f};

    for (int t = 0; t < T_; t++) {
        #pragma unroll
        for (int r = 0; r < 4; r++) {
            int c = c0 + ty + 8 * r;
            float xv = x[(((size_t)t * B_ + b) * C_ + c) * (size_t)N_ + n0 + tx];
            float vv = v[r];
            vv = fmaf(xv - vv, 0.5f, vv);
            float sp = (vv >= 1.0f) ? 1.f : 0.f;
            v[r] = (vv >= 1.0f) ? 0.f : vv;
            s[ty + 8 * r][tx] = sp;
        }
        __syncthreads();
        int tb = t * B_ + b;
        #pragma unroll
        for (int r = 0; r < 4; r++) {
            int nl = warp * 4 + r;
            uint32_t word = __ballot_sync(FULLW, s[lane][nl] != 0.f);
            if (lane == 0)
                g_bx[((size_t)tb * N_ + n0 + nl) * 16 + (c0 >> 5)] = word;
        }
        __syncthreads();
    }
}

// ---------------------------------------------------------------------------
// List decode from 16 mask words (deterministic, ascending c). 128 threads.
// ---------------------------------------------------------------------------
__device__ __forceinline__ int decode_list(const uint32_t* __restrict__ gmask,
                                           uint16_t* list, uint32_t* maskw,
                                           int* basew, int* cntp)
{
    int tid = threadIdx.x, warp = tid >> 5, lane = tid & 31;
    if (tid < 16) maskw[tid] = gmask[tid];
    __syncthreads();
    if (tid == 0) {
        int s = 0;
        #pragma unroll
        for (int ci = 0; ci < 16; ci++) { basew[ci] = s; s += __popc(maskw[ci]); }
        *cntp = s;
    }
    __syncthreads();
    #pragma unroll
    for (int ci = warp; ci < 16; ci += 4) {
        uint32_t m = maskw[ci];
        if (m & (1u << lane))
            list[basew[ci] + __popc(m & ((1u << lane) - 1u))] = (uint16_t)(ci * 32 + lane);
    }
    __syncthreads();
    return *cntp;
}

// ---------------------------------------------------------------------------
// Pack 4 spike bits/thread into 16 words across 128 threads, store to gmem.
// ---------------------------------------------------------------------------
__device__ __forceinline__ void store_bits(uint32_t* __restrict__ grow,
                                           uint32_t nib, int tid, int lane)
{
    uint32_t contrib = nib << (4 * (lane & 7));
    contrib |= __shfl_xor_sync(FULLW, contrib, 1);
    contrib |= __shfl_xor_sync(FULLW, contrib, 2);
    contrib |= __shfl_xor_sync(FULLW, contrib, 4);
    if ((lane & 7) == 0) grow[tid >> 3] = contrib;
}

// ---------------------------------------------------------------------------
// Fused Q/K/V gather-GEMM + BN + LIF (vth=1) -> spike BITS.  (R12 version)
// Block = (b, n); loops t with LIF state in registers.
// ---------------------------------------------------------------------------
__global__ __launch_bounds__(128)
void gather_qkv_lif_kernel(const float* __restrict__ qg, const float* __restrict__ qb,
                           const float* __restrict__ qm, const float* __restrict__ qv,
                           const float* __restrict__ kg, const float* __restrict__ kb,
                           const float* __restrict__ km, const float* __restrict__ kv,
                           const float* __restrict__ vg, const float* __restrict__ vb,
                           const float* __restrict__ vm, const float* __restrict__ vv)
{
    int b = blockIdx.y, n = blockIdx.x;
    int tid = threadIdx.x, lane = tid & 31;

    __shared__ uint16_t list[C_];
    __shared__ uint32_t maskw[16];
    __shared__ int basew[16];
    __shared__ int cnt;

    const float4* Wq4 = (const float4*)(g_wt + 0 * (size_t)CC);
    const float4* Wk4 = (const float4*)(g_wt + 1 * (size_t)CC);
    const float4* Wv4 = (const float4*)(g_wt + 2 * (size_t)CC);

    float4 qs_c, qs_h, ks_c, ks_h, vs_c, vs_h;
    {
        float4 g = ((const float4*)qg)[tid], bb = ((const float4*)qb)[tid];
        float4 m = ((const float4*)qm)[tid], v = ((const float4*)qv)[tid];
        qs_c.x = g.x * rsqrtf(v.x + EPS_); qs_h.x = bb.x - m.x * qs_c.x;
        qs_c.y = g.y * rsqrtf(v.y + EPS_); qs_h.y = bb.y - m.y * qs_c.y;
        qs_c.z = g.z * rsqrtf(v.z + EPS_); qs_h.z = bb.z - m.z * qs_c.z;
        qs_c.w = g.w * rsqrtf(v.w + EPS_); qs_h.w = bb.w - m.w * qs_c.w;
    }
    {
        float4 g = ((const float4*)kg)[tid], bb = ((const float4*)kb)[tid];
        float4 m = ((const float4*)km)[tid], v = ((const float4*)kv)[tid];
        ks_c.x = g.x * rsqrtf(v.x + EPS_); ks_h.x = bb.x - m.x * ks_c.x;
        ks_c.y = g.y * rsqrtf(v.y + EPS_); ks_h.y = bb.y - m.y * ks_c.y;
        ks_c.z = g.z * rsqrtf(v.z + EPS_); ks_h.z = bb.z - m.z * ks_c.z;
        ks_c.w = g.w * rsqrtf(v.w + EPS_); ks_h.w = bb.w - m.w * ks_c.w;
    }
    {
        float4 g = ((const float4*)vg)[tid], bb = ((const float4*)vb)[tid];
        float4 m = ((const float4*)vm)[tid], v = ((const float4*)vv)[tid];
        vs_c.x = g.x * rsqrtf(v.x + EPS_); vs_h.x = bb.x - m.x * vs_c.x;
        vs_c.y = g.y * rsqrtf(v.y + EPS_); vs_h.y = bb.y - m.y * vs_c.y;
        vs_c.z = g.z * rsqrtf(v.z + EPS_); vs_h.z = bb.z - m.z * vs_c.z;
        vs_c.w = g.w * rsqrtf(v.w + EPS_); vs_h.w = bb.w - m.w * vs_c.w;
    }

    float4 mq = {0.f,0.f,0.f,0.f}, mk = mq, mv = mq;

    for (int t = 0; t < T_; t++) {
        int tb = t * B_ + b;
        size_t rbase = ((size_t)tb * N_ + n) * 16;
        int count = decode_list(g_bx + rbase, list, maskw, basew, &cnt);

        float4 aq = {0.f,0.f,0.f,0.f}, ak = aq, av = aq;
        for (int i = 0; i < count; i++) {
            int c = list[i];
            float4 wq = Wq4[(size_t)c * 128 + tid];
            float4 wk = Wk4[(size_t)c * 128 + tid];
            float4 wv = Wv4[(size_t)c * 128 + tid];
            aq.x += wq.x; aq.y += wq.y; aq.z += wq.z; aq.w += wq.w;
            ak.x += wk.x; ak.y += wk.y; ak.z += wk.z; ak.w += wk.w;
            av.x += wv.x; av.y += wv.y; av.z += wv.z; av.w += wv.w;
        }

        {
            float y0 = aq.x * qs_c.x + qs_h.x, y1 = aq.y * qs_c.y + qs_h.y;
            float y2 = aq.z * qs_c.z + qs_h.z, y3 = aq.w * qs_c.w + qs_h.w;
            uint32_t nib = 0;
            mq.x = fmaf(y0 - mq.x, 0.5f, mq.x); nib |= (mq.x >= 1.f) ? 1u : 0u; mq.x = (mq.x >= 1.f) ? 0.f : mq.x;
            mq.y = fmaf(y1 - mq.y, 0.5f, mq.y); nib |= (mq.y >= 1.f) ? 2u : 0u; mq.y = (mq.y >= 1.f) ? 0.f : mq.y;
            mq.z = fmaf(y2 - mq.z, 0.5f, mq.z); nib |= (mq.z >= 1.f) ? 4u : 0u; mq.z = (mq.z >= 1.f) ? 0.f : mq.z;
            mq.w = fmaf(y3 - mq.w, 0.5f, mq.w); nib |= (mq.w >= 1.f) ? 8u : 0u; mq.w = (mq.w >= 1.f) ? 0.f : mq.w;
            store_bits(g_bq + rbase, nib, tid, lane);
        }
        {
            float y0 = ak.x * ks_c.x + ks_h.x, y1 = ak.y * ks_c.y + ks_h.y;
            float y2 = ak.z * ks_c.z + ks_h.z, y3 = ak.w * ks_c.w + ks_h.w;
            uint32_t nib = 0;
            mk.x = fmaf(y0 - mk.x, 0.5f, mk.x); nib |= (mk.x >= 1.f) ? 1u : 0u; mk.x = (mk.x >= 1.f) ? 0.f : mk.x;
            mk.y = fmaf(y1 - mk.y, 0.5f, mk.y); nib |= (mk.y >= 1.f) ? 2u : 0u; mk.y = (mk.y >= 1.f) ? 0.f : mk.y;
            mk.z = fmaf(y2 - mk.z, 0.5f, mk.z); nib |= (mk.z >= 1.f) ? 4u : 0u; mk.z = (mk.z >= 1.f) ? 0.f : mk.z;
            mk.w = fmaf(y3 - mk.w, 0.5f, mk.w); nib |= (mk.w >= 1.f) ? 8u : 0u; mk.w = (mk.w >= 1.f) ? 0.f : mk.w;
            store_bits(g_bk + rbase, nib, tid, lane);
        }
        {
            float y0 = av.x * vs_c.x + vs_h.x, y1 = av.y * vs_c.y + vs_h.y;
            float y2 = av.z * vs_c.z + vs_h.z, y3 = av.w * vs_c.w + vs_h.w;
            uint32_t nib = 0;
            mv.x = fmaf(y0 - mv.x, 0.5f, mv.x); nib |= (mv.x >= 1.f) ? 1u : 0u; mv.x = (mv.x >= 1.f) ? 0.f : mv.x;
            mv.y = fmaf(y1 - mv.y, 0.5f, mv.y); nib |= (mv.y >= 1.f) ? 2u : 0u; mv.y = (mv.y >= 1.f) ? 0.f : mv.y;
            mv.z = fmaf(y2 - mv.z, 0.5f, mv.z); nib |= (mv.z >= 1.f) ? 4u : 0u; mv.z = (mv.z >= 1.f) ? 0.f : mv.z;
            mv.w = fmaf(y3 - mv.w, 0.5f, mv.w); nib |= (mv.w >= 1.f) ? 8u : 0u; mv.w = (mv.w >= 1.f) ? 0.f : mv.w;
            store_bits(g_bv + rbase, nib, tid, lane);
        }
    }
}

// ---------------------------------------------------------------------------
// KV[e][dd] = 0.125 * popc-sum over n of k_e & v_dd, per (tb,h) — exact.
// Inline 32x32 bit-transpose from g_bk/g_bv (c-words {2h,2h+1} only; the
// (tb,h) blocks partition the transpose work disjointly). Padded smem rows
// ([64][33]) make the popc-phase MV reads conflict-free.
// ---------------------------------------------------------------------------
__global__ __launch_bounds__(256)
void kv_popc_kernel()
{
    int idx = blockIdx.x;                   // tb*8 + h
    int tb = idx >> 3, h = idx & 7;
    float* KVb = g_kv + (size_t)idx * HD_ * HD_;

    __shared__ uint32_t MK[64][33];
    __shared__ uint32_t MV[64][33];

    int tid = threadIdx.x, lane = tid & 31, wid = tid >> 5;

    // transpose fill: 64 warp-tiles (cwl 0..1, nw 0..31), 8 per warp
    for (int i = wid; i < 64; i += 8) {
        int cwl = i >> 5, nw = i & 31;
        int cw = 2 * h + cwl;
        uint32_t wk = g_bk[((size_t)tb * N_ + nw * 32 + lane) * 16 + cw];
        uint32_t wv = g_bv[((size_t)tb * N_ + nw * 32 + lane) * 16 + cw];
        uint32_t myk = 0, myv = 0;
        #pragma unroll
        for (int j = 0; j < 32; j++) {
            uint32_t bk_ = __ballot_sync(FULLW, (wk >> j) & 1u);
            uint32_t bv_ = __ballot_sync(FULLW, (wv >> j) & 1u);
            if (lane == j) { myk = bk_; myv = bv_; }
        }
        MK[cwl * 32 + lane][nw] = myk;
        MV[cwl * 32 + lane][nw] = myv;
    }
    __syncthreads();

    #pragma unroll
    for (int r = 0; r < 16; r++) {
        int p = r * 256 + tid;              // 0..4095
        int e = p >> 6, dd = p & 63;
        int s = 0;
        #pragma unroll
        for (int w = 0; w < 32; w++)
            s += __popc(MK[e][w] & MV[dd][w]);
        KVb[(size_t)e * HD_ + dd] = (float)s * 0.125f;
    }
}

// ---------------------------------------------------------------------------
// FUSED: attention-apply + attn-LIF (vth=0.5) + projection gather + bias + BN.
// (R12 version: block = (b, n), loops t; writes g_ot [tb][n][c] coalesced.)
// ---------------------------------------------------------------------------
__global__ __launch_bounds__(128)
void attn_proj_lif_kernel(const float* __restrict__ bp,
                          const float* __restrict__ pg, const float* __restrict__ pb,
                          const float* __restrict__ pm, const float* __restrict__ pv)
{
    int b = blockIdx.y, n = blockIdx.x;
    int tid = threadIdx.x, warp = tid >> 5, lane = tid & 31;
    int h = tid >> 4;
    int q4i = tid & 15;

    __shared__ uint16_t list[C_];
    __shared__ uint32_t maskw[16];
    __shared__ int basew[16];
    __shared__ int cnt;

    const float4* Wp4 = (const float4*)(g_wt + 3 * (size_t)CC);

    float4 sc, sh;
    {
        float4 g = ((const float4*)pg)[tid], bb = ((const float4*)pb)[tid];
        float4 m = ((const float4*)pm)[tid], v = ((const float4*)pv)[tid];
        float4 bi = ((const float4*)bp)[tid];
        sc.x = g.x * rsqrtf(v.x + EPS_); sh.x = bb.x + (bi.x - m.x) * sc.x;
        sc.y = g.y * rsqrtf(v.y + EPS_); sh.y = bb.y + (bi.y - m.y) * sc.y;
        sc.z = g.z * rsqrtf(v.z + EPS_); sh.z = bb.z + (bi.z - m.z) * sc.z;
        sc.w = g.w * rsqrtf(v.w + EPS_); sh.w = bb.w + (bi.w - m.w) * sc.w;
    }

    float4 mo = {0.f, 0.f, 0.f, 0.f};

    for (int t = 0; t < T_; t++) {
        int tb = t * B_ + b;
        size_t rbase = ((size_t)tb * N_ + n) * 16;

        uint32_t qw0 = g_bq[rbase + 2 * h];
        uint32_t qw1 = g_bq[rbase + 2 * h + 1];
        const float4* KVb = (const float4*)(g_kv + (size_t)(tb * NH_ + h) * HD_ * HD_);

        float4 a = {0.f, 0.f, 0.f, 0.f};
        uint32_t m = qw0;
        while (m) {
            int e = __ffs(m) - 1; m &= m - 1;
            float4 kvv = KVb[e * 16 + q4i];
            a.x += kvv.x; a.y += kvv.y; a.z += kvv.z; a.w += kvv.w;
        }
        m = qw1;
        while (m) {
            int e = __ffs(m) - 1; m &= m - 1;
            float4 kvv = KVb[(32 + e) * 16 + q4i];
            a.x += kvv.x; a.y += kvv.y; a.z += kvv.z; a.w += kvv.w;
        }

        uint32_t nib = 0;
        mo.x = fmaf(a.x - mo.x, 0.5f, mo.x); nib |= (mo.x >= 0.5f) ? 1u : 0u; mo.x = (mo.x >= 0.5f) ? 0.f : mo.x;
        mo.y = fmaf(a.y - mo.y, 0.5f, mo.y); nib |= (mo.y >= 0.5f) ? 2u : 0u; mo.y = (mo.y >= 0.5f) ? 0.f : mo.y;
        mo.z = fmaf(a.z - mo.z, 0.5f, mo.z); nib |= (mo.z >= 0.5f) ? 4u : 0u; mo.z = (mo.z >= 0.5f) ? 0.f : mo.z;
        mo.w = fmaf(a.w - mo.w, 0.5f, mo.w); nib |= (mo.w >= 0.5f) ? 8u : 0u; mo.w = (mo.w >= 0.5f) ? 0.f : mo.w;

        uint32_t contrib = nib << (4 * (lane & 7));
        contrib |= __shfl_xor_sync(FULLW, contrib, 1);
        contrib |= __shfl_xor_sync(FULLW, contrib, 2);
        contrib |= __shfl_xor_sync(FULLW, contrib, 4);
        if ((lane & 7) == 0) maskw[tid >> 3] = contrib;
        __syncthreads();

        if (tid == 0) {
            int s = 0;
            #pragma unroll
            for (int ci = 0; ci < 16; ci++) { basew[ci] = s; s += __popc(maskw[ci]); }
            cnt = s;
        }
        __syncthreads();
        #pragma unroll
        for (int ci = warp; ci < 16; ci += 4) {
            uint32_t mm = maskw[ci];
            if (mm & (1u << lane))
                list[basew[ci] + __popc(mm & ((1u << lane) - 1u))] = (uint16_t)(ci * 32 + lane);
        }
        __syncthreads();
        int count = cnt;

        float4 ap = {0.f, 0.f, 0.f, 0.f};
        for (int i = 0; i < count; i++) {
            int c = list[i];
            float4 wp = Wp4[(size_t)c * 128 + tid];
            ap.x += wp.x; ap.y += wp.y; ap.z += wp.z; ap.w += wp.w;
        }

        float4 o;
        o.x = ap.x * sc.x + sh.x;
        o.y = ap.y * sc.y + sh.y;
        o.z = ap.z * sc.z + sh.z;
        o.w = ap.w * sc.w + sh.w;
        ((float4*)(g_ot + ((size_t)tb * N_ + n) * C_))[tid] = o;
        __syncthreads();
    }
}

// ---------------------------------------------------------------------------
// Final transpose: g_ot [tb][n][c] -> out [tb][c][n]   (R12 version)
// ---------------------------------------------------------------------------
__global__ __launch_bounds__(256)
void transpose_out_kernel(float* __restrict__ out)
{
    int tb = blockIdx.z;
    int n0 = blockIdx.y * 32;
    int c0 = blockIdx.x * 32;
    int tx = threadIdx.x & 31, ty = threadIdx.x >> 5;
    __shared__ float s[32][33];
    const float* src = g_ot + (size_t)tb * N_ * C_;
    float* dst = out + (size_t)tb * C_ * N_;
    #pragma unroll
    for (int r = 0; r < 4; r++)
        s[ty + 8 * r][tx] = src[(size_t)(n0 + ty + 8 * r) * C_ + c0 + tx];
    __syncthreads();
    #pragma unroll
    for (int r = 0; r < 4; r++)
        dst[(size_t)(c0 + ty + 8 * r) * N_ + n0 + tx] = s[tx][ty + 8 * r];
}

// ---------------------------------------------------------------------------
// Launch
// ---------------------------------------------------------------------------
extern "C" void kernel_launch(void* const* d_in, const int* in_sizes, int n_in,
                              void* d_out, int out_size)
{
    const float* x   = (const float*)d_in[0];
    const float* Wq  = (const float*)d_in[1];
    const float* q_g = (const float*)d_in[2];
    const float* q_b = (const float*)d_in[3];
    const float* q_m = (const float*)d_in[4];
    const float* q_v = (const float*)d_in[5];
    const float* Wk  = (const float*)d_in[6];
    const float* k_g = (const float*)d_in[7];
    const float* k_b = (const float*)d_in[8];
    const float* k_m = (const float*)d_in[9];
    const float* k_v = (const float*)d_in[10];
    const float* Wv  = (const float*)d_in[11];
    const float* v_g = (const float*)d_in[12];
    const float* v_b = (const float*)d_in[13];
    const float* v_m = (const float*)d_in[14];
    const float* v_v = (const float*)d_in[15];
    const float* Wp  = (const float*)d_in[16];
    const float* bp  = (const float*)d_in[17];
    const float* p_g = (const float*)d_in[18];
    const float* p_b = (const float*)d_in[19];
    const float* p_m = (const float*)d_in[20];
    const float* p_v = (const float*)d_in[21];
    float* out = (float*)d_out;

    prep_wt_kernel<<<dim3(C_ / 32, C_ / 32, 4), 256>>>(Wq, Wk, Wv, Wp);
    lif_in_bits_kernel<<<dim3(N_ / 32, C_ / 32, B_), 256>>>(x);
    gather_qkv_lif_kernel<<<dim3(N_, B_), 128>>>(
        q_g, q_b, q_m, q_v, k_g, k_b, k_m, k_v, v_g, v_b, v_m, v_v);
    kv_popc_kernel<<<TBAT * NH_, 256>>>();
    attn_proj_lif_kernel<<<dim3(N_, B_), 128>>>(bp, p_g, p_b, p_m, p_v);
    transpose_out_kernel<<<dim3(C_ / 32, N_ / 32, TBAT), 256>>>(out);
}

// round 17
// speedup vs baseline: 1.2504x; 1.0087x over previous
#include <cuda_runtime.h>
#include <cstdint>

// ---------------------------------------------------------------------------
// Problem constants
// ---------------------------------------------------------------------------
#define T_  4
#define B_  4
#define C_  512
#define N_  1024          // H*W
#define NH_ 8
#define HD_ 64
#define TBAT (T_*B_)
#define BCN  (B_*C_*N_)
#define CC   (C_*C_)
#define EPS_ 1e-5f
#define FULLW 0xffffffffu

// ---------------------------------------------------------------------------
// Device scratch (static — no allocation anywhere)
// Spikes live as bitmasks: row layout [tb][n][16 c-words] (bit = c&31).
// ---------------------------------------------------------------------------
__device__ float    g_wt[4 * CC];          // W^T per branch: [w][c][d]
__device__ uint32_t g_bx[TBAT * N_ * 16];  // input spike bits
__device__ uint32_t g_bq[TBAT * N_ * 16];  // q spike bits
__device__ uint32_t g_bk[TBAT * N_ * 16];  // k spike bits
__device__ uint32_t g_bv[TBAT * N_ * 16];  // v spike bits
__device__ float    g_ot[T_ * BCN];        // proj output [tb][n][c]
__device__ float    g_kv[TBAT * NH_ * HD_ * HD_];  // [tb*8+h][e][dd], carries x0.125

// ---------------------------------------------------------------------------
// Weight transpose (all 4 branches): W[d][c] -> g_wt[w][c][d]
// ---------------------------------------------------------------------------
__global__ __launch_bounds__(256)
void prep_wt_kernel(const float* __restrict__ Wq, const float* __restrict__ Wk,
                    const float* __restrict__ Wv, const float* __restrict__ Wp)
{
    int w = blockIdx.z;
    const float* src = (w == 0) ? Wq : (w == 1) ? Wk : (w == 2) ? Wv : Wp;
    float* dst = g_wt + (size_t)w * CC;
    int d0 = blockIdx.y * 32, c0 = blockIdx.x * 32;
    int tx = threadIdx.x & 31, ty = threadIdx.x >> 5;
    __shared__ float s[32][33];
    #pragma unroll
    for (int r = 0; r < 4; r++)
        s[ty + 8 * r][tx] = src[(size_t)(d0 + ty + 8 * r) * C_ + c0 + tx];
    __syncthreads();
    #pragma unroll
    for (int r = 0; r < 4; r++)
        dst[(size_t)(c0 + ty + 8 * r) * C_ + d0 + tx] = s[tx][ty + 8 * r];
}

// ---------------------------------------------------------------------------
// Input LIF -> spike BITS.  x fp32 [t,b,c,n] -> g_bx[tb][n][c-word], vth=1.
// ---------------------------------------------------------------------------
__global__ __launch_bounds__(256)
void lif_in_bits_kernel(const float* __restrict__ x)
{
    int b  = blockIdx.z;
    int c0 = blockIdx.y * 32;
    int n0 = blockIdx.x * 32;
    int tx = threadIdx.x & 31, ty = threadIdx.x >> 5;
    int warp = threadIdx.x >> 5, lane = threadIdx.x & 31;
    __shared__ float s[32][33];
    float v[4] = {0.f, 0.f, 0.f, 0.f};

    for (int t = 0; t < T_; t++) {
        #pragma unroll
        for (int r = 0; r < 4; r++) {
            int c = c0 + ty + 8 * r;
            float xv = x[(((size_t)t * B_ + b) * C_ + c) * (size_t)N_ + n0 + tx];
            float vv = v[r];
            vv = fmaf(xv - vv, 0.5f, vv);
            float sp = (vv >= 1.0f) ? 1.f : 0.f;
            v[r] = (vv >= 1.0f) ? 0.f : vv;
            s[ty + 8 * r][tx] = sp;
        }
        __syncthreads();
        int tb = t * B_ + b;
        #pragma unroll
        for (int r = 0; r < 4; r++) {
            int nl = warp * 4 + r;
            uint32_t word = __ballot_sync(FULLW, s[lane][nl] != 0.f);
            if (lane == 0)
                g_bx[((size_t)tb * N_ + n0 + nl) * 16 + (c0 >> 5)] = word;
        }
        __syncthreads();
    }
}

// ---------------------------------------------------------------------------
// List decode from 16 mask words (deterministic, ascending c). 128 threads.
// ---------------------------------------------------------------------------
__device__ __forceinline__ int decode_list(const uint32_t* __restrict__ gmask,
                                           uint16_t* list, uint32_t* maskw,
                                           int* basew, int* cntp)
{
    int tid = threadIdx.x, warp = tid >> 5, lane = tid & 31;
    if (tid < 16) maskw[tid] = gmask[tid];
    __syncthreads();
    if (tid == 0) {
        int s = 0;
        #pragma unroll
        for (int ci = 0; ci < 16; ci++) { basew[ci] = s; s += __popc(maskw[ci]); }
        *cntp = s;
    }
    __syncthreads();
    #pragma unroll
    for (int ci = warp; ci < 16; ci += 4) {
        uint32_t m = maskw[ci];
        if (m & (1u << lane))
            list[basew[ci] + __popc(m & ((1u << lane) - 1u))] = (uint16_t)(ci * 32 + lane);
    }
    __syncthreads();
    return *cntp;
}

// ---------------------------------------------------------------------------
// Pack 4 spike bits/thread into 16 words across 128 threads, store to gmem.
// ---------------------------------------------------------------------------
__device__ __forceinline__ void store_bits(uint32_t* __restrict__ grow,
                                           uint32_t nib, int tid, int lane)
{
    uint32_t contrib = nib << (4 * (lane & 7));
    contrib |= __shfl_xor_sync(FULLW, contrib, 1);
    contrib |= __shfl_xor_sync(FULLW, contrib, 2);
    contrib |= __shfl_xor_sync(FULLW, contrib, 4);
    if ((lane & 7) == 0) grow[tid >> 3] = contrib;
}

// ---------------------------------------------------------------------------
// Fused Q/K/V gather-GEMM + BN + LIF (vth=1) -> spike BITS.
// Block = (b, n); loops t with LIF state in registers.
// ---------------------------------------------------------------------------
__global__ __launch_bounds__(128)
void gather_qkv_lif_kernel(const float* __restrict__ qg, const float* __restrict__ qb,
                           const float* __restrict__ qm, const float* __restrict__ qv,
                           const float* __restrict__ kg, const float* __restrict__ kb,
                           const float* __restrict__ km, const float* __restrict__ kv,
                           const float* __restrict__ vg, const float* __restrict__ vb,
                           const float* __restrict__ vm, const float* __restrict__ vv)
{
    int b = blockIdx.y, n = blockIdx.x;
    int tid = threadIdx.x, lane = tid & 31;

    __shared__ uint16_t list[C_];
    __shared__ uint32_t maskw[16];
    __shared__ int basew[16];
    __shared__ int cnt;

    const float4* Wq4 = (const float4*)(g_wt + 0 * (size_t)CC);
    const float4* Wk4 = (const float4*)(g_wt + 1 * (size_t)CC);
    const float4* Wv4 = (const float4*)(g_wt + 2 * (size_t)CC);

    float4 qs_c, qs_h, ks_c, ks_h, vs_c, vs_h;
    {
        float4 g = ((const float4*)qg)[tid], bb = ((const float4*)qb)[tid];
        float4 m = ((const float4*)qm)[tid], v = ((const float4*)qv)[tid];
        qs_c.x = g.x * rsqrtf(v.x + EPS_); qs_h.x = bb.x - m.x * qs_c.x;
        qs_c.y = g.y * rsqrtf(v.y + EPS_); qs_h.y = bb.y - m.y * qs_c.y;
        qs_c.z = g.z * rsqrtf(v.z + EPS_); qs_h.z = bb.z - m.z * qs_c.z;
        qs_c.w = g.w * rsqrtf(v.w + EPS_); qs_h.w = bb.w - m.w * qs_c.w;
    }
    {
        float4 g = ((const float4*)kg)[tid], bb = ((const float4*)kb)[tid];
        float4 m = ((const float4*)km)[tid], v = ((const float4*)kv)[tid];
        ks_c.x = g.x * rsqrtf(v.x + EPS_); ks_h.x = bb.x - m.x * ks_c.x;
        ks_c.y = g.y * rsqrtf(v.y + EPS_); ks_h.y = bb.y - m.y * ks_c.y;
        ks_c.z = g.z * rsqrtf(v.z + EPS_); ks_h.z = bb.z - m.z * ks_c.z;
        ks_c.w = g.w * rsqrtf(v.w + EPS_); ks_h.w = bb.w - m.w * ks_c.w;
    }
    {
        float4 g = ((const float4*)vg)[tid], bb = ((const float4*)vb)[tid];
        float4 m = ((const float4*)vm)[tid], v = ((const float4*)vv)[tid];
        vs_c.x = g.x * rsqrtf(v.x + EPS_); vs_h.x = bb.x - m.x * vs_c.x;
        vs_c.y = g.y * rsqrtf(v.y + EPS_); vs_h.y = bb.y - m.y * vs_c.y;
        vs_c.z = g.z * rsqrtf(v.z + EPS_); vs_h.z = bb.z - m.z * vs_c.z;
        vs_c.w = g.w * rsqrtf(v.w + EPS_); vs_h.w = bb.w - m.w * vs_c.w;
    }

    float4 mq = {0.f,0.f,0.f,0.f}, mk = mq, mv = mq;

    for (int t = 0; t < T_; t++) {
        int tb = t * B_ + b;
        size_t rbase = ((size_t)tb * N_ + n) * 16;
        int count = decode_list(g_bx + rbase, list, maskw, basew, &cnt);

        float4 aq = {0.f,0.f,0.f,0.f}, ak = aq, av = aq;
        for (int i = 0; i < count; i++) {
            int c = list[i];
            float4 wq = Wq4[(size_t)c * 128 + tid];
            float4 wk = Wk4[(size_t)c * 128 + tid];
            float4 wv = Wv4[(size_t)c * 128 + tid];
            aq.x += wq.x; aq.y += wq.y; aq.z += wq.z; aq.w += wq.w;
            ak.x += wk.x; ak.y += wk.y; ak.z += wk.z; ak.w += wk.w;
            av.x += wv.x; av.y += wv.y; av.z += wv.z; av.w += wv.w;
        }

        {
            float y0 = aq.x * qs_c.x + qs_h.x, y1 = aq.y * qs_c.y + qs_h.y;
            float y2 = aq.z * qs_c.z + qs_h.z, y3 = aq.w * qs_c.w + qs_h.w;
            uint32_t nib = 0;
            mq.x = fmaf(y0 - mq.x, 0.5f, mq.x); nib |= (mq.x >= 1.f) ? 1u : 0u; mq.x = (mq.x >= 1.f) ? 0.f : mq.x;
            mq.y = fmaf(y1 - mq.y, 0.5f, mq.y); nib |= (mq.y >= 1.f) ? 2u : 0u; mq.y = (mq.y >= 1.f) ? 0.f : mq.y;
            mq.z = fmaf(y2 - mq.z, 0.5f, mq.z); nib |= (mq.z >= 1.f) ? 4u : 0u; mq.z = (mq.z >= 1.f) ? 0.f : mq.z;
            mq.w = fmaf(y3 - mq.w, 0.5f, mq.w); nib |= (mq.w >= 1.f) ? 8u : 0u; mq.w = (mq.w >= 1.f) ? 0.f : mq.w;
            store_bits(g_bq + rbase, nib, tid, lane);
        }
        {
            float y0 = ak.x * ks_c.x + ks_h.x, y1 = ak.y * ks_c.y + ks_h.y;
            float y2 = ak.z * ks_c.z + ks_h.z, y3 = ak.w * ks_c.w + ks_h.w;
            uint32_t nib = 0;
            mk.x = fmaf(y0 - mk.x, 0.5f, mk.x); nib |= (mk.x >= 1.f) ? 1u : 0u; mk.x = (mk.x >= 1.f) ? 0.f : mk.x;
            mk.y = fmaf(y1 - mk.y, 0.5f, mk.y); nib |= (mk.y >= 1.f) ? 2u : 0u; mk.y = (mk.y >= 1.f) ? 0.f : mk.y;
            mk.z = fmaf(y2 - mk.z, 0.5f, mk.z); nib |= (mk.z >= 1.f) ? 4u : 0u; mk.z = (mk.z >= 1.f) ? 0.f : mk.z;
            mk.w = fmaf(y3 - mk.w, 0.5f, mk.w); nib |= (mk.w >= 1.f) ? 8u : 0u; mk.w = (mk.w >= 1.f) ? 0.f : mk.w;
            store_bits(g_bk + rbase, nib, tid, lane);
        }
        {
            float y0 = av.x * vs_c.x + vs_h.x, y1 = av.y * vs_c.y + vs_h.y;
            float y2 = av.z * vs_c.z + vs_h.z, y3 = av.w * vs_c.w + vs_h.w;
            uint32_t nib = 0;
            mv.x = fmaf(y0 - mv.x, 0.5f, mv.x); nib |= (mv.x >= 1.f) ? 1u : 0u; mv.x = (mv.x >= 1.f) ? 0.f : mv.x;
            mv.y = fmaf(y1 - mv.y, 0.5f, mv.y); nib |= (mv.y >= 1.f) ? 2u : 0u; mv.y = (mv.y >= 1.f) ? 0.f : mv.y;
            mv.z = fmaf(y2 - mv.z, 0.5f, mv.z); nib |= (mv.z >= 1.f) ? 4u : 0u; mv.z = (mv.z >= 1.f) ? 0.f : mv.z;
            mv.w = fmaf(y3 - mv.w, 0.5f, mv.w); nib |= (mv.w >= 1.f) ? 8u : 0u; mv.w = (mv.w >= 1.f) ? 0.f : mv.w;
            store_bits(g_bv + rbase, nib, tid, lane);
        }
    }
}

// ---------------------------------------------------------------------------
// KV[e][dd] = 0.125 * popc-sum over n of k_e & v_dd, per (tb,h) — exact.
// Inline bit-transpose (c-words {2h,2h+1}); 512 threads for latency hiding:
// fill = 4 tiles/warp, popc phase = 8 outputs/thread.
// ---------------------------------------------------------------------------
__global__ __launch_bounds__(512)
void kv_popc_kernel()
{
    int idx = blockIdx.x;                   // tb*8 + h
    int tb = idx >> 3, h = idx & 7;
    float* KVb = g_kv + (size_t)idx * HD_ * HD_;

    __shared__ uint32_t MK[64][33];
    __shared__ uint32_t MV[64][33];

    int tid = threadIdx.x, lane = tid & 31, wid = tid >> 5;   // 16 warps

    // transpose fill: 64 warp-tiles (cwl 0..1, nw 0..31), 4 per warp
    for (int i = wid; i < 64; i += 16) {
        int cwl = i >> 5, nw = i & 31;
        int cw = 2 * h + cwl;
        uint32_t wk = g_bk[((size_t)tb * N_ + nw * 32 + lane) * 16 + cw];
        uint32_t wv = g_bv[((size_t)tb * N_ + nw * 32 + lane) * 16 + cw];
        uint32_t myk = 0, myv = 0;
        #pragma unroll
        for (int j = 0; j < 32; j++) {
            uint32_t bk_ = __ballot_sync(FULLW, (wk >> j) & 1u);
            uint32_t bv_ = __ballot_sync(FULLW, (wv >> j) & 1u);
            if (lane == j) { myk = bk_; myv = bv_; }
        }
        MK[cwl * 32 + lane][nw] = myk;
        MV[cwl * 32 + lane][nw] = myv;
    }
    __syncthreads();

    #pragma unroll
    for (int r = 0; r < 8; r++) {
        int p = r * 512 + tid;              // 0..4095
        int e = p >> 6, dd = p & 63;
        int s = 0;
        #pragma unroll
        for (int w = 0; w < 32; w++)
            s += __popc(MK[e][w] & MV[dd][w]);
        KVb[(size_t)e * HD_ + dd] = (float)s * 0.125f;
    }
}

// ---------------------------------------------------------------------------
// FUSED: attention-apply + attn-LIF (vth=0.5) + projection gather + bias + BN.
// Block = (b, n), loops t; writes g_ot [tb][n][c] coalesced.
// ---------------------------------------------------------------------------
__global__ __launch_bounds__(128)
void attn_proj_lif_kernel(const float* __restrict__ bp,
                          const float* __restrict__ pg, const float* __restrict__ pb,
                          const float* __restrict__ pm, const float* __restrict__ pv)
{
    int b = blockIdx.y, n = blockIdx.x;
    int tid = threadIdx.x, warp = tid >> 5, lane = tid & 31;
    int h = tid >> 4;
    int q4i = tid & 15;

    __shared__ uint16_t list[C_];
    __shared__ uint32_t maskw[16];
    __shared__ int basew[16];
    __shared__ int cnt;

    const float4* Wp4 = (const float4*)(g_wt + 3 * (size_t)CC);

    float4 sc, sh;
    {
        float4 g = ((const float4*)pg)[tid], bb = ((const float4*)pb)[tid];
        float4 m = ((const float4*)pm)[tid], v = ((const float4*)pv)[tid];
        float4 bi = ((const float4*)bp)[tid];
        sc.x = g.x * rsqrtf(v.x + EPS_); sh.x = bb.x + (bi.x - m.x) * sc.x;
        sc.y = g.y * rsqrtf(v.y + EPS_); sh.y = bb.y + (bi.y - m.y) * sc.y;
        sc.z = g.z * rsqrtf(v.z + EPS_); sh.z = bb.z + (bi.z - m.z) * sc.z;
        sc.w = g.w * rsqrtf(v.w + EPS_); sh.w = bb.w + (bi.w - m.w) * sc.w;
    }

    float4 mo = {0.f, 0.f, 0.f, 0.f};

    for (int t = 0; t < T_; t++) {
        int tb = t * B_ + b;
        size_t rbase = ((size_t)tb * N_ + n) * 16;

        uint32_t qw0 = g_bq[rbase + 2 * h];
        uint32_t qw1 = g_bq[rbase + 2 * h + 1];
        const float4* KVb = (const float4*)(g_kv + (size_t)(tb * NH_ + h) * HD_ * HD_);

        float4 a = {0.f, 0.f, 0.f, 0.f};
        uint32_t m = qw0;
        while (m) {
            int e = __ffs(m) - 1; m &= m - 1;
            float4 kvv = KVb[e * 16 + q4i];
            a.x += kvv.x; a.y += kvv.y; a.z += kvv.z; a.w += kvv.w;
        }
        m = qw1;
        while (m) {
            int e = __ffs(m) - 1; m &= m - 1;
            float4 kvv = KVb[(32 + e) * 16 + q4i];
            a.x += kvv.x; a.y += kvv.y; a.z += kvv.z; a.w += kvv.w;
        }

        uint32_t nib = 0;
        mo.x = fmaf(a.x - mo.x, 0.5f, mo.x); nib |= (mo.x >= 0.5f) ? 1u : 0u; mo.x = (mo.x >= 0.5f) ? 0.f : mo.x;
        mo.y = fmaf(a.y - mo.y, 0.5f, mo.y); nib |= (mo.y >= 0.5f) ? 2u : 0u; mo.y = (mo.y >= 0.5f) ? 0.f : mo.y;
        mo.z = fmaf(a.z - mo.z, 0.5f, mo.z); nib |= (mo.z >= 0.5f) ? 4u : 0u; mo.z = (mo.z >= 0.5f) ? 0.f : mo.z;
        mo.w = fmaf(a.w - mo.w, 0.5f, mo.w); nib |= (mo.w >= 0.5f) ? 8u : 0u; mo.w = (mo.w >= 0.5f) ? 0.f : mo.w;

        uint32_t contrib = nib << (4 * (lane & 7));
        contrib |= __shfl_xor_sync(FULLW, contrib, 1);
        contrib |= __shfl_xor_sync(FULLW, contrib, 2);
        contrib |= __shfl_xor_sync(FULLW, contrib, 4);
        if ((lane & 7) == 0) maskw[tid >> 3] = contrib;
        __syncthreads();

        if (tid == 0) {
            int s = 0;
            #pragma unroll
            for (int ci = 0; ci < 16; ci++) { basew[ci] = s; s += __popc(maskw[ci]); }
            cnt = s;
        }
        __syncthreads();
        #pragma unroll
        for (int ci = warp; ci < 16; ci += 4) {
            uint32_t mm = maskw[ci];
            if (mm & (1u << lane))
                list[basew[ci] + __popc(mm & ((1u << lane) - 1u))] = (uint16_t)(ci * 32 + lane);
        }
        __syncthreads();
        int count = cnt;

        float4 ap = {0.f, 0.f, 0.f, 0.f};
        for (int i = 0; i < count; i++) {
            int c = list[i];
            float4 wp = Wp4[(size_t)c * 128 + tid];
            ap.x += wp.x; ap.y += wp.y; ap.z += wp.z; ap.w += wp.w;
        }

        float4 o;
        o.x = ap.x * sc.x + sh.x;
        o.y = ap.y * sc.y + sh.y;
        o.z = ap.z * sc.z + sh.z;
        o.w = ap.w * sc.w + sh.w;
        ((float4*)(g_ot + ((size_t)tb * N_ + n) * C_))[tid] = o;
        __syncthreads();
    }
}

// ---------------------------------------------------------------------------
// Final transpose: g_ot [tb][n][c] -> out [tb][c][n]
// ---------------------------------------------------------------------------
__global__ __launch_bounds__(256)
void transpose_out_kernel(float* __restrict__ out)
{
    int tb = blockIdx.z;
    int n0 = blockIdx.y * 32;
    int c0 = blockIdx.x * 32;
    int tx = threadIdx.x & 31, ty = threadIdx.x >> 5;
    __shared__ float s[32][33];
    const float* src = g_ot + (size_t)tb * N_ * C_;
    float* dst = out + (size_t)tb * C_ * N_;
    #pragma unroll
    for (int r = 0; r < 4; r++)
        s[ty + 8 * r][tx] = src[(size_t)(n0 + ty + 8 * r) * C_ + c0 + tx];
    __syncthreads();
    #pragma unroll
    for (int r = 0; r < 4; r++)
        dst[(size_t)(c0 + ty + 8 * r) * N_ + n0 + tx] = s[tx][ty + 8 * r];
}

// ---------------------------------------------------------------------------
// Launch
// ---------------------------------------------------------------------------
extern "C" void kernel_launch(void* const* d_in, const int* in_sizes, int n_in,
                              void* d_out, int out_size)
{
    const float* x   = (const float*)d_in[0];
    const float* Wq  = (const float*)d_in[1];
    const float* q_g = (const float*)d_in[2];
    const float* q_b = (const float*)d_in[3];
    const float* q_m = (const float*)d_in[4];
    const float* q_v = (const float*)d_in[5];
    const float* Wk  = (const float*)d_in[6];
    const float* k_g = (const float*)d_in[7];
    const float* k_b = (const float*)d_in[8];
    const float* k_m = (const float*)d_in[9];
    const float* k_v = (const float*)d_in[10];
    const float* Wv  = (const float*)d_in[11];
    const float* v_g = (const float*)d_in[12];
    const float* v_b = (const float*)d_in[13];
    const float* v_m = (const float*)d_in[14];
    const float* v_v = (const float*)d_in[15];
    const float* Wp  = (const float*)d_in[16];
    const float* bp  = (const float*)d_in[17];
    const float* p_g = (const float*)d_in[18];
    const float* p_b = (const float*)d_in[19];
    const float* p_m = (const float*)d_in[20];
    const float* p_v = (const float*)d_in[21];
    float* out = (float*)d_out;

    prep_wt_kernel<<<dim3(C_ / 32, C_ / 32, 4), 256>>>(Wq, Wk, Wv, Wp);
    lif_in_bits_kernel<<<dim3(N_ / 32, C_ / 32, B_), 256>>>(x);
    gather_qkv_lif_kernel<<<dim3(N_, B_), 128>>>(
        q_g, q_b, q_m, q_v, k_g, k_b, k_m, k_v, v_g, v_b, v_m, v_v);
    kv_popc_kernel<<<TBAT * NH_, 512>>>();
    attn_proj_lif_kernel<<<dim3(N_, B_), 128>>>(bp, p_g, p_b, p_m, p_v);
    transpose_out_kernel<<<dim3(C_ / 32, N_ / 32, TBAT), 256>>>(out);
}